// round 7
// baseline (speedup 1.0000x reference)
#include <cuda_runtime.h>
#include <cuda_bf16.h>
#include <cstdint>
#include <cstddef>

#define BATCH 16
#define NPTS  8192
#define NSAMP 1024
#define NGRP  32
#define FDIM  64

// ---------------- device scratch ----------------
__device__ float g_xs[BATCH][NPTS];
__device__ float g_ys[BATCH][NPTS];
__device__ float g_zs[BATCH][NPTS];
__device__ float g_ss[BATCH][NPTS];
__device__ int   g_fps[BATCH][NSAMP];
__device__ int   g_grp[BATCH][NSAMP][NGRP];

// ---------------- stage 0: SoA + sumsq prep ----------------
__global__ void prep_kernel(const float* __restrict__ xyz) {
    int i = blockIdx.x * blockDim.x + threadIdx.x;
    if (i >= BATCH * NPTS) return;
    int b = i >> 13, n = i & (NPTS - 1);
    float x = xyz[3 * i + 0], y = xyz[3 * i + 1], z = xyz[3 * i + 2];
    g_xs[b][n] = x; g_ys[b][n] = y; g_zs[b][n] = z;
    g_ss[b][n] = __fmaf_rn(z, z, __fmaf_rn(y, y, __fmul_rn(x, x)));
}

// ---------------- packed f32x2 helpers (Blackwell FFMA2/FADD2/FMUL2) -------
static __device__ __forceinline__ unsigned long long pk2(float lo, float hi) {
    unsigned long long r;
    asm("mov.b64 %0, {%1, %2};" : "=l"(r) : "f"(lo), "f"(hi));
    return r;
}
static __device__ __forceinline__ void upk2(unsigned long long v, float& lo, float& hi) {
    asm("mov.b64 {%0, %1}, %2;" : "=f"(lo), "=f"(hi) : "l"(v));
}
static __device__ __forceinline__ unsigned long long add2(unsigned long long a,
                                                          unsigned long long b) {
    unsigned long long r;
    asm("add.rn.f32x2 %0, %1, %2;" : "=l"(r) : "l"(a), "l"(b));
    return r;
}
static __device__ __forceinline__ unsigned long long mul2(unsigned long long a,
                                                          unsigned long long b) {
    unsigned long long r;
    asm("mul.rn.f32x2 %0, %1, %2;" : "=l"(r) : "l"(a), "l"(b));
    return r;
}
static __device__ __forceinline__ unsigned long long fma2(unsigned long long a,
                                                          unsigned long long b,
                                                          unsigned long long c) {
    unsigned long long r;
    asm("fma.rn.f32x2 %0, %1, %2, %3;" : "=l"(r) : "l"(a), "l"(b), "l"(c));
    return r;
}

// ---------------- stage 1: FPS (packed-f32x2 issue-slimmed) ----------------
// One block per batch, 1024 threads, 8 pts/thread. Points held NEGATED and
// pair-packed in 64-bit regs: dx = add2(negP, C) = c-x, and (c-x)^2 is
// bit-identical to (x-c)^2 under the same fma chain -> matches reference.
// Argmax: track max VALUE only (FMNMX); the rare matching thread re-scans its
// 8 dists for the lowest matching global index after the warp REDUX.
__global__ __launch_bounds__(1024) void fps_kernel(float* __restrict__ out_sampled) {
    extern __shared__ float sdyn[];
    float* sx = sdyn;
    float* sy = sdyn + NPTS;
    float* sz = sdyn + 2 * NPTS;
    __shared__ uint2 s_wk[2][32];

    int b = blockIdx.x;
    int t = threadIdx.x;
    int lane = t & 31, warp = t >> 5;
    const float* xs = g_xs[b];
    const float* ys = g_ys[b];
    const float* zs = g_zs[b];

    unsigned long long nX[4], nY[4], nZ[4];   // negated, packed pairs
    float dist[8];
    {
        float x[8], y[8], z[8];
#pragma unroll
        for (int j = 0; j < 8; j++) {
            int p = t + 1024 * j;
            x[j] = xs[p]; y[j] = ys[p]; z[j] = zs[p];
            sx[p] = x[j]; sy[p] = y[j]; sz[p] = z[j];
            dist[j] = 1e10f;
        }
#pragma unroll
        for (int q = 0; q < 4; q++) {
            nX[q] = pk2(-x[2 * q], -x[2 * q + 1]);
            nY[q] = pk2(-y[2 * q], -y[2 * q + 1]);
            nZ[q] = pk2(-z[2 * q], -z[2 * q + 1]);
        }
    }
    __syncthreads();

    int far = 0;
    for (int k = 0; k < NSAMP; k++) {
        if (t == 0) {
            g_fps[b][k] = far;
            size_t o = ((size_t)b * NSAMP + k) * 3;
            out_sampled[o + 0] = sx[far];
            out_sampled[o + 1] = sy[far];
            out_sampled[o + 2] = sz[far];
        }
        float cx = sx[far], cy = sy[far], cz = sz[far];
        unsigned long long C_x = pk2(cx, cx);
        unsigned long long C_y = pk2(cy, cy);
        unsigned long long C_z = pk2(cz, cz);

        float tmax = 0.f;
#pragma unroll
        for (int q = 0; q < 4; q++) {
            unsigned long long dx = add2(nX[q], C_x);   // c - x
            unsigned long long dy = add2(nY[q], C_y);
            unsigned long long dz = add2(nZ[q], C_z);
            unsigned long long d = fma2(dz, dz, fma2(dy, dy, mul2(dx, dx)));
            float d0, d1;
            upk2(d, d0, d1);
            float m0 = fminf(dist[2 * q],     d0);
            float m1 = fminf(dist[2 * q + 1], d1);
            dist[2 * q] = m0; dist[2 * q + 1] = m1;
            tmax = fmaxf(tmax, fmaxf(m0, m1));
        }
        unsigned tb = __float_as_uint(tmax);            // >=0: u32 order == float
        unsigned wmax = __reduce_max_sync(0xffffffffu, tb);
        unsigned cand = 0xffffffffu;
        if (tb == wmax) {
#pragma unroll 1
            for (int j = 7; j >= 0; j--)
                if (__float_as_uint(dist[j]) == wmax) cand = (unsigned)(t + 1024 * j);
        }
        unsigned widx = __reduce_min_sync(0xffffffffu, cand);
        if (lane == 0) s_wk[k & 1][warp] = make_uint2(wmax, widx);
        __syncthreads();
        uint2 v = s_wk[k & 1][lane];
        unsigned m2 = __reduce_max_sync(0xffffffffu, v.x);
        unsigned c2 = (v.x == m2) ? v.y : 0xffffffffu;
        far = (int)__reduce_min_sync(0xffffffffu, c2);
    }
}

// ---------------- stage 2: ball query (unchanged) ----------------
__global__ __launch_bounds__(256) void ballq_kernel() {
    int w = threadIdx.x >> 5, lane = threadIdx.x & 31;
    int gs = blockIdx.x * 8 + w;
    int b = gs >> 10, s = gs & 1023;

    int far = g_fps[b][s];
    float ax = g_xs[b][far], ay = g_ys[b][far], az = g_zs[b][far];
    float sa = __fmaf_rn(az, az, __fmaf_rn(ay, ay, __fmul_rn(ax, ax)));
    const float RR = 0.04f;

    int filled = 0;
    for (int base = 0; base < NPTS; base += 32) {
        int n = base + lane;
        float bx = g_xs[b][n], by = g_ys[b][n], bz = g_zs[b][n], sb = g_ss[b][n];
        float dot = __fmaf_rn(az, bz, __fmaf_rn(ay, by, __fmul_rn(ax, bx)));
        float sq = __fsub_rn(__fadd_rn(sa, sb), __fmul_rn(2.0f, dot));
        bool inr = !(sq > RR);
        unsigned m = __ballot_sync(0xffffffffu, inr);
        int pos = filled + __popc(m & ((1u << lane) - 1u));
        if (inr && pos < NGRP) g_grp[b][s][pos] = n;
        filled += __popc(m);
        if (filled >= NGRP) break;
    }
    if (filled < NGRP) {
        __syncwarp();
        int first = g_grp[b][s][0];
        int j = filled + lane;
        if (j < NGRP) g_grp[b][s][j] = first;
    }
}

// =====================================================================
// stage 3: warp-MMA fused MLP + maxpool (unchanged from R6 passing)
// =====================================================================
#define LDA       136
#define ABUF_HI   0
#define ABUF_LO   34816
#define WBUF_HI   69632
#define WBUF_LO   88064
#define SMEM_TOT  106496

static __device__ __forceinline__ uint32_t smem_u32(const void* p) {
    uint32_t a;
    asm("{ .reg .u64 t; cvta.to.shared.u64 t, %1; cvt.u32.u64 %0, t; }"
        : "=r"(a) : "l"(p));
    return a;
}
static __device__ __forceinline__ void ldm_x4(uint32_t* r, uint32_t addr) {
    asm volatile("ldmatrix.sync.aligned.m8n8.x4.shared.b16 {%0,%1,%2,%3}, [%4];"
                 : "=r"(r[0]), "=r"(r[1]), "=r"(r[2]), "=r"(r[3]) : "r"(addr));
}
static __device__ __forceinline__ void mma_bf16(float* c, const uint32_t* a,
                                                uint32_t b0, uint32_t b1) {
    asm volatile(
        "mma.sync.aligned.m16n8k16.row.col.f32.bf16.bf16.f32 "
        "{%0,%1,%2,%3}, {%4,%5,%6,%7}, {%8,%9}, {%0,%1,%2,%3};"
        : "+f"(c[0]), "+f"(c[1]), "+f"(c[2]), "+f"(c[3])
        : "r"(a[0]), "r"(a[1]), "r"(a[2]), "r"(a[3]), "r"(b0), "r"(b1));
}

static __device__ __forceinline__ void split2(float a, float b,
                                              unsigned& hi, unsigned& lo) {
    __nv_bfloat16 ha = __float2bfloat16(a), hb = __float2bfloat16(b);
    float ra = a - __bfloat162float(ha), rb = b - __bfloat162float(hb);
    __nv_bfloat16 la = __float2bfloat16(ra), lb = __float2bfloat16(rb);
    hi = (unsigned)__bfloat16_as_ushort(ha) | ((unsigned)__bfloat16_as_ushort(hb) << 16);
    lo = (unsigned)__bfloat16_as_ushort(la) | ((unsigned)__bfloat16_as_ushort(lb) << 16);
}
static __device__ __forceinline__ void storeA(char* smp, int row, int col,
                                              float a, float b) {
    unsigned h, l;
    split2(a, b, h, l);
    int off = (row * LDA + col) * 2;
    *(unsigned*)(smp + ABUF_HI + off) = h;
    *(unsigned*)(smp + ABUF_LO + off) = l;
}
template <int K, int N, int LDSRC, int KPAD, int LDWS>
static __device__ __forceinline__ void stageW(char* smp, const float* W, int srcOff,
                                              int tid0, int nthr) {
    for (int idx = tid0; idx < KPAD * N; idx += nthr) {
        int k = idx / N, n = idx - k * N;
        float w = (k < K) ? __ldg(W + k * LDSRC + srcOff + n) : 0.f;
        __nv_bfloat16 h = __float2bfloat16(w);
        float rr = w - __bfloat162float(h);
        __nv_bfloat16 l = __float2bfloat16(rr);
        int off = (n * LDWS + k) * 2;
        *(__nv_bfloat16*)(smp + WBUF_HI + off) = h;
        *(__nv_bfloat16*)(smp + WBUF_LO + off) = l;
    }
}

template <int NBLK, int KSTEPS, int LDWS>
static __device__ __forceinline__ void warp_gemm(uint32_t sb, int rowBase, int nOff,
                                                 float (&acc)[2][NBLK][4]) {
    int lane = threadIdx.x & 31;
#pragma unroll
    for (int m = 0; m < 2; m++)
#pragma unroll
        for (int nb = 0; nb < NBLK; nb++)
#pragma unroll
            for (int i = 0; i < 4; i++) acc[m][nb][i] = 0.f;

    int arow = lane & 15;
    int acolo = (lane >> 4) << 3;
    int bRow = nOff + ((lane >> 4) & 1) * 8 + (lane & 7);
    int bK = lane & 8;

#pragma unroll
    for (int k = 0; k < KSTEPS; k++) {
        int k0 = k << 4;
        uint32_t ah[2][4], al[2][4];
#pragma unroll
        for (int m = 0; m < 2; m++) {
            uint32_t ao = (uint32_t)(((rowBase + m * 16 + arow) * LDA + k0 + acolo) * 2);
            ldm_x4(ah[m], sb + ABUF_HI + ao);
            ldm_x4(al[m], sb + ABUF_LO + ao);
        }
#pragma unroll
        for (int p = 0; p < NBLK / 2; p++) {
            uint32_t wo = (uint32_t)(((bRow + p * 16) * LDWS + k0 + bK) * 2);
            uint32_t bh[4], bl[4];
            ldm_x4(bh, sb + WBUF_HI + wo);
            ldm_x4(bl, sb + WBUF_LO + wo);
#pragma unroll
            for (int m = 0; m < 2; m++) {
                mma_bf16(acc[m][2 * p],     ah[m], bh[0], bh[1]);
                mma_bf16(acc[m][2 * p],     ah[m], bl[0], bl[1]);
                mma_bf16(acc[m][2 * p],     al[m], bh[0], bh[1]);
                mma_bf16(acc[m][2 * p + 1], ah[m], bh[2], bh[3]);
                mma_bf16(acc[m][2 * p + 1], ah[m], bl[2], bl[3]);
                mma_bf16(acc[m][2 * p + 1], al[m], bh[2], bh[3]);
            }
        }
    }
}

template <int NBLK>
static __device__ __forceinline__ void epi_store(char* smp, int rowBase, int colBase,
                                                 const float* __restrict__ bias,
                                                 float (&acc)[2][NBLK][4]) {
    int lane = threadIdx.x & 31;
    int cq = (lane & 3) * 2;
    int rq = lane >> 2;
#pragma unroll
    for (int nb = 0; nb < NBLK; nb++) {
        int col = colBase + nb * 8 + cq;
        float b0 = __ldg(bias + col), b1 = __ldg(bias + col + 1);
#pragma unroll
        for (int m = 0; m < 2; m++) {
            int row = rowBase + m * 16 + rq;
            float v0 = fmaxf(acc[m][nb][0] + b0, 0.f);
            float v1 = fmaxf(acc[m][nb][1] + b1, 0.f);
            float v2 = fmaxf(acc[m][nb][2] + b0, 0.f);
            float v3 = fmaxf(acc[m][nb][3] + b1, 0.f);
            storeA(smp, row, col, v0, v1);
            storeA(smp, row + 8, col, v2, v3);
        }
    }
}

static __device__ __forceinline__ void epi_max(int gColBase, const float* __restrict__ B3,
                                               float* __restrict__ out, size_t obase,
                                               float (&acc)[2][4][4]) {
    int lane = threadIdx.x & 31;
    int cq = (lane & 3) * 2;
#pragma unroll
    for (int nb = 0; nb < 4; nb++) {
        int col = gColBase + nb * 8 + cq;
        float b0 = __ldg(B3 + col), b1 = __ldg(B3 + col + 1);
        float v0 = fmaxf(fmaxf(acc[0][nb][0], acc[0][nb][2]),
                         fmaxf(acc[1][nb][0], acc[1][nb][2])) + b0;
        float v1 = fmaxf(fmaxf(acc[0][nb][1], acc[0][nb][3]),
                         fmaxf(acc[1][nb][1], acc[1][nb][3])) + b1;
        v0 = fmaxf(v0, 0.f); v1 = fmaxf(v1, 0.f);
#pragma unroll
        for (int off = 4; off <= 16; off <<= 1) {
            v0 = fmaxf(v0, __shfl_xor_sync(0xffffffffu, v0, off));
            v1 = fmaxf(v1, __shfl_xor_sync(0xffffffffu, v1, off));
        }
        if (lane < 4) {
            out[obase + col] = v0;
            out[obase + col + 1] = v1;
        }
    }
}

__global__ void __launch_bounds__(256, 2) mlp_kernel(
    const float* __restrict__ fea,
    const float* __restrict__ W1, const float* __restrict__ B1,
    const float* __restrict__ W2, const float* __restrict__ B2,
    const float* __restrict__ W3, const float* __restrict__ B3,
    float* __restrict__ out)
{
    extern __shared__ char smp[];
    uint32_t sb = smem_u32(smp);
    int tid = threadIdx.x, wid = tid >> 5;
    int b = blockIdx.y, s0 = blockIdx.x * 4;
    int cent = wid >> 1, nhalf = wid & 1;
    int rowBase = cent * 32;

    if (tid < 128) {
        int c = tid >> 5, g = tid & 31, s = s0 + c;
        int far = g_fps[b][s];
        int idx = g_grp[b][s][g];
        float f[80];
        f[0] = g_xs[b][idx] - g_xs[b][far];
        f[1] = g_ys[b][idx] - g_ys[b][far];
        f[2] = g_zs[b][idx] - g_zs[b][far];
        const float4* fr = (const float4*)(fea + ((size_t)b * NPTS + idx) * FDIM);
#pragma unroll
        for (int q = 0; q < 16; q++) {
            float4 v = __ldg(fr + q);
            f[3 + 4 * q + 0] = v.x; f[3 + 4 * q + 1] = v.y;
            f[3 + 4 * q + 2] = v.z; f[3 + 4 * q + 3] = v.w;
        }
#pragma unroll
        for (int q = 67; q < 80; q++) f[q] = 0.f;
#pragma unroll
        for (int q = 0; q < 40; q++) storeA(smp, tid, 2 * q, f[2 * q], f[2 * q + 1]);
    } else {
        stageW<67, 64, 64, 80, 88>(smp, W1, 0, tid - 128, 128);
    }
    __syncthreads();

    {
        float acc[2][4][4];
        warp_gemm<4, 5, 88>(sb, rowBase, nhalf * 32, acc);
        __syncthreads();
        epi_store<4>(smp, rowBase, nhalf * 32, B1, acc);
        stageW<64, 128, 128, 64, 72>(smp, W2, 0, tid, 256);
        __syncthreads();
    }

    {
        float acc[2][8][4];
        warp_gemm<8, 4, 72>(sb, rowBase, nhalf * 64, acc);
        __syncthreads();
        epi_store<8>(smp, rowBase, nhalf * 64, B2, acc);
        stageW<128, 64, 256, 128, 136>(smp, W3, 0, tid, 256);
        __syncthreads();
    }

    size_t obase = (size_t)BATCH * NSAMP * 3 +
                   ((size_t)(b * NSAMP + s0 + cent)) * 256;
    {
        float acc[2][4][4];
        warp_gemm<4, 8, 136>(sb, rowBase, nhalf * 32, acc);
        epi_max(nhalf * 32, B3, out, obase, acc);
        __syncthreads();
        stageW<128, 64, 256, 128, 136>(smp, W3, 64, tid, 256);
        __syncthreads();
        warp_gemm<4, 8, 136>(sb, rowBase, nhalf * 32, acc);
        epi_max(64 + nhalf * 32, B3, out, obase, acc);
        __syncthreads();
        stageW<128, 64, 256, 128, 136>(smp, W3, 128, tid, 256);
        __syncthreads();
        warp_gemm<4, 8, 136>(sb, rowBase, nhalf * 32, acc);
        epi_max(128 + nhalf * 32, B3, out, obase, acc);
        __syncthreads();
        stageW<128, 64, 256, 128, 136>(smp, W3, 192, tid, 256);
        __syncthreads();
        warp_gemm<4, 8, 136>(sb, rowBase, nhalf * 32, acc);
        epi_max(192 + nhalf * 32, B3, out, obase, acc);
    }
}

// ---------------- launcher ----------------
extern "C" void kernel_launch(void* const* d_in, const int* in_sizes, int n_in,
                              void* d_out, int out_size) {
    (void)in_sizes; (void)n_in; (void)out_size;
    const float* xyz = (const float*)d_in[0];
    const float* fea = (const float*)d_in[1];
    const float* W1  = (const float*)d_in[2];
    const float* B1  = (const float*)d_in[3];
    const float* W2  = (const float*)d_in[4];
    const float* B2  = (const float*)d_in[5];
    const float* W3  = (const float*)d_in[6];
    const float* B3  = (const float*)d_in[7];
    float* out = (float*)d_out;

    cudaFuncSetAttribute(mlp_kernel, cudaFuncAttributeMaxDynamicSharedMemorySize,
                         SMEM_TOT);
    cudaFuncSetAttribute(fps_kernel, cudaFuncAttributeMaxDynamicSharedMemorySize,
                         3 * NPTS * 4);

    prep_kernel<<<(BATCH * NPTS + 255) / 256, 256>>>(xyz);
    fps_kernel<<<BATCH, 1024, 3 * NPTS * 4>>>(out);
    ballq_kernel<<<BATCH * NSAMP / 8, 256>>>();
    dim3 grid(NSAMP / 4, BATCH);
    mlp_kernel<<<grid, 256, SMEM_TOT>>>(fea, W1, B1, W2, B2, W3, B3, out);
}

// round 8
// speedup vs baseline: 1.6088x; 1.6088x over previous
#include <cuda_runtime.h>
#include <cuda_bf16.h>
#include <cstdint>
#include <cstddef>

#define BATCH 16
#define NPTS  8192
#define NSAMP 1024
#define NGRP  32
#define FDIM  64

// ---------------- device scratch ----------------
__device__ float g_xs[BATCH][NPTS];
__device__ float g_ys[BATCH][NPTS];
__device__ float g_zs[BATCH][NPTS];
__device__ float g_ss[BATCH][NPTS];
__device__ int   g_fps[BATCH][NSAMP];
__device__ int   g_grp[BATCH][NSAMP][NGRP];

// ---------------- stage 0: SoA + sumsq prep ----------------
__global__ void prep_kernel(const float* __restrict__ xyz) {
    int i = blockIdx.x * blockDim.x + threadIdx.x;
    if (i >= BATCH * NPTS) return;
    int b = i >> 13, n = i & (NPTS - 1);
    float x = xyz[3 * i + 0], y = xyz[3 * i + 1], z = xyz[3 * i + 2];
    g_xs[b][n] = x; g_ys[b][n] = y; g_zs[b][n] = z;
    g_ss[b][n] = __fmaf_rn(z, z, __fmaf_rn(y, y, __fmul_rn(x, x)));
}

// ---------------- stage 1: FPS (scalar, value-only argmax tracking) --------
// One block per batch, 1024 threads, 8 pts/thread in registers; xyz mirrored
// in smem for LDS centroid fetch. Hot loop tracks only the running max dist
// (1 FMAX/pt); the rare thread whose local max equals the warp REDUX max
// re-derives its lowest matching index via an unrolled predicated chain.
__global__ __launch_bounds__(1024) void fps_kernel(float* __restrict__ out_sampled) {
    extern __shared__ float sdyn[];
    float* sx = sdyn;
    float* sy = sdyn + NPTS;
    float* sz = sdyn + 2 * NPTS;
    __shared__ uint2 s_wk[2][32];

    int b = blockIdx.x;
    int t = threadIdx.x;
    int lane = t & 31, warp = t >> 5;
    const float* xs = g_xs[b];
    const float* ys = g_ys[b];
    const float* zs = g_zs[b];

    float px[8], py[8], pz[8], dist[8];
#pragma unroll
    for (int j = 0; j < 8; j++) {
        int p = t + 1024 * j;
        float x = xs[p], y = ys[p], z = zs[p];
        px[j] = x; py[j] = y; pz[j] = z;
        sx[p] = x; sy[p] = y; sz[p] = z;
        dist[j] = 1e10f;
    }
    __syncthreads();

    int far = 0;
    for (int k = 0; k < NSAMP; k++) {
        if (t == 0) {
            g_fps[b][k] = far;
            size_t o = ((size_t)b * NSAMP + k) * 3;
            out_sampled[o + 0] = sx[far];
            out_sampled[o + 1] = sy[far];
            out_sampled[o + 2] = sz[far];
        }
        float cx = sx[far], cy = sy[far], cz = sz[far];

        float tmax = 0.f;
#pragma unroll
        for (int j = 0; j < 8; j++) {
            float dx = __fsub_rn(px[j], cx);
            float dy = __fsub_rn(py[j], cy);
            float dz = __fsub_rn(pz[j], cz);
            float d = __fmaf_rn(dz, dz, __fmaf_rn(dy, dy, __fmul_rn(dx, dx)));
            float dm = fminf(dist[j], d);
            dist[j] = dm;
            tmax = fmaxf(tmax, dm);
        }
        unsigned tb = __float_as_uint(tmax);           // >=0: u32 order == float
        unsigned wmax = __reduce_max_sync(0xffffffffu, tb);
        unsigned cand = 0xffffffffu;
        if (tb == wmax) {
            // unrolled descending scan: final value = lowest matching j
#pragma unroll
            for (int j = 7; j >= 0; j--)
                cand = (__float_as_uint(dist[j]) == wmax) ? (unsigned)(t + 1024 * j)
                                                          : cand;
        }
        unsigned widx = __reduce_min_sync(0xffffffffu, cand);
        if (lane == 0) s_wk[k & 1][warp] = make_uint2(wmax, widx);
        __syncthreads();
        uint2 v = s_wk[k & 1][lane];
        unsigned m2 = __reduce_max_sync(0xffffffffu, v.x);
        unsigned c2 = (v.x == m2) ? v.y : 0xffffffffu;
        far = (int)__reduce_min_sync(0xffffffffu, c2);
    }
}

// ---------------- stage 2: ball query (unchanged) ----------------
__global__ __launch_bounds__(256) void ballq_kernel() {
    int w = threadIdx.x >> 5, lane = threadIdx.x & 31;
    int gs = blockIdx.x * 8 + w;
    int b = gs >> 10, s = gs & 1023;

    int far = g_fps[b][s];
    float ax = g_xs[b][far], ay = g_ys[b][far], az = g_zs[b][far];
    float sa = __fmaf_rn(az, az, __fmaf_rn(ay, ay, __fmul_rn(ax, ax)));
    const float RR = 0.04f;

    int filled = 0;
    for (int base = 0; base < NPTS; base += 32) {
        int n = base + lane;
        float bx = g_xs[b][n], by = g_ys[b][n], bz = g_zs[b][n], sb = g_ss[b][n];
        float dot = __fmaf_rn(az, bz, __fmaf_rn(ay, by, __fmul_rn(ax, bx)));
        float sq = __fsub_rn(__fadd_rn(sa, sb), __fmul_rn(2.0f, dot));
        bool inr = !(sq > RR);
        unsigned m = __ballot_sync(0xffffffffu, inr);
        int pos = filled + __popc(m & ((1u << lane) - 1u));
        if (inr && pos < NGRP) g_grp[b][s][pos] = n;
        filled += __popc(m);
        if (filled >= NGRP) break;
    }
    if (filled < NGRP) {
        __syncwarp();
        int first = g_grp[b][s][0];
        int j = filled + lane;
        if (j < NGRP) g_grp[b][s][j] = first;
    }
}

// =====================================================================
// stage 3: warp-MMA fused MLP + maxpool (unchanged from R6 passing)
// =====================================================================
#define LDA       136
#define ABUF_HI   0
#define ABUF_LO   34816
#define WBUF_HI   69632
#define WBUF_LO   88064
#define SMEM_TOT  106496

static __device__ __forceinline__ uint32_t smem_u32(const void* p) {
    uint32_t a;
    asm("{ .reg .u64 t; cvta.to.shared.u64 t, %1; cvt.u32.u64 %0, t; }"
        : "=r"(a) : "l"(p));
    return a;
}
static __device__ __forceinline__ void ldm_x4(uint32_t* r, uint32_t addr) {
    asm volatile("ldmatrix.sync.aligned.m8n8.x4.shared.b16 {%0,%1,%2,%3}, [%4];"
                 : "=r"(r[0]), "=r"(r[1]), "=r"(r[2]), "=r"(r[3]) : "r"(addr));
}
static __device__ __forceinline__ void mma_bf16(float* c, const uint32_t* a,
                                                uint32_t b0, uint32_t b1) {
    asm volatile(
        "mma.sync.aligned.m16n8k16.row.col.f32.bf16.bf16.f32 "
        "{%0,%1,%2,%3}, {%4,%5,%6,%7}, {%8,%9}, {%0,%1,%2,%3};"
        : "+f"(c[0]), "+f"(c[1]), "+f"(c[2]), "+f"(c[3])
        : "r"(a[0]), "r"(a[1]), "r"(a[2]), "r"(a[3]), "r"(b0), "r"(b1));
}

static __device__ __forceinline__ void split2(float a, float b,
                                              unsigned& hi, unsigned& lo) {
    __nv_bfloat16 ha = __float2bfloat16(a), hb = __float2bfloat16(b);
    float ra = a - __bfloat162float(ha), rb = b - __bfloat162float(hb);
    __nv_bfloat16 la = __float2bfloat16(ra), lb = __float2bfloat16(rb);
    hi = (unsigned)__bfloat16_as_ushort(ha) | ((unsigned)__bfloat16_as_ushort(hb) << 16);
    lo = (unsigned)__bfloat16_as_ushort(la) | ((unsigned)__bfloat16_as_ushort(lb) << 16);
}
static __device__ __forceinline__ void storeA(char* smp, int row, int col,
                                              float a, float b) {
    unsigned h, l;
    split2(a, b, h, l);
    int off = (row * LDA + col) * 2;
    *(unsigned*)(smp + ABUF_HI + off) = h;
    *(unsigned*)(smp + ABUF_LO + off) = l;
}
template <int K, int N, int LDSRC, int KPAD, int LDWS>
static __device__ __forceinline__ void stageW(char* smp, const float* W, int srcOff,
                                              int tid0, int nthr) {
    for (int idx = tid0; idx < KPAD * N; idx += nthr) {
        int k = idx / N, n = idx - k * N;
        float w = (k < K) ? __ldg(W + k * LDSRC + srcOff + n) : 0.f;
        __nv_bfloat16 h = __float2bfloat16(w);
        float rr = w - __bfloat162float(h);
        __nv_bfloat16 l = __float2bfloat16(rr);
        int off = (n * LDWS + k) * 2;
        *(__nv_bfloat16*)(smp + WBUF_HI + off) = h;
        *(__nv_bfloat16*)(smp + WBUF_LO + off) = l;
    }
}

template <int NBLK, int KSTEPS, int LDWS>
static __device__ __forceinline__ void warp_gemm(uint32_t sb, int rowBase, int nOff,
                                                 float (&acc)[2][NBLK][4]) {
    int lane = threadIdx.x & 31;
#pragma unroll
    for (int m = 0; m < 2; m++)
#pragma unroll
        for (int nb = 0; nb < NBLK; nb++)
#pragma unroll
            for (int i = 0; i < 4; i++) acc[m][nb][i] = 0.f;

    int arow = lane & 15;
    int acolo = (lane >> 4) << 3;
    int bRow = nOff + ((lane >> 4) & 1) * 8 + (lane & 7);
    int bK = lane & 8;

#pragma unroll
    for (int k = 0; k < KSTEPS; k++) {
        int k0 = k << 4;
        uint32_t ah[2][4], al[2][4];
#pragma unroll
        for (int m = 0; m < 2; m++) {
            uint32_t ao = (uint32_t)(((rowBase + m * 16 + arow) * LDA + k0 + acolo) * 2);
            ldm_x4(ah[m], sb + ABUF_HI + ao);
            ldm_x4(al[m], sb + ABUF_LO + ao);
        }
#pragma unroll
        for (int p = 0; p < NBLK / 2; p++) {
            uint32_t wo = (uint32_t)(((bRow + p * 16) * LDWS + k0 + bK) * 2);
            uint32_t bh[4], bl[4];
            ldm_x4(bh, sb + WBUF_HI + wo);
            ldm_x4(bl, sb + WBUF_LO + wo);
#pragma unroll
            for (int m = 0; m < 2; m++) {
                mma_bf16(acc[m][2 * p],     ah[m], bh[0], bh[1]);
                mma_bf16(acc[m][2 * p],     ah[m], bl[0], bl[1]);
                mma_bf16(acc[m][2 * p],     al[m], bh[0], bh[1]);
                mma_bf16(acc[m][2 * p + 1], ah[m], bh[2], bh[3]);
                mma_bf16(acc[m][2 * p + 1], ah[m], bl[2], bl[3]);
                mma_bf16(acc[m][2 * p + 1], al[m], bh[2], bh[3]);
            }
        }
    }
}

template <int NBLK>
static __device__ __forceinline__ void epi_store(char* smp, int rowBase, int colBase,
                                                 const float* __restrict__ bias,
                                                 float (&acc)[2][NBLK][4]) {
    int lane = threadIdx.x & 31;
    int cq = (lane & 3) * 2;
    int rq = lane >> 2;
#pragma unroll
    for (int nb = 0; nb < NBLK; nb++) {
        int col = colBase + nb * 8 + cq;
        float b0 = __ldg(bias + col), b1 = __ldg(bias + col + 1);
#pragma unroll
        for (int m = 0; m < 2; m++) {
            int row = rowBase + m * 16 + rq;
            float v0 = fmaxf(acc[m][nb][0] + b0, 0.f);
            float v1 = fmaxf(acc[m][nb][1] + b1, 0.f);
            float v2 = fmaxf(acc[m][nb][2] + b0, 0.f);
            float v3 = fmaxf(acc[m][nb][3] + b1, 0.f);
            storeA(smp, row, col, v0, v1);
            storeA(smp, row + 8, col, v2, v3);
        }
    }
}

static __device__ __forceinline__ void epi_max(int gColBase, const float* __restrict__ B3,
                                               float* __restrict__ out, size_t obase,
                                               float (&acc)[2][4][4]) {
    int lane = threadIdx.x & 31;
    int cq = (lane & 3) * 2;
#pragma unroll
    for (int nb = 0; nb < 4; nb++) {
        int col = gColBase + nb * 8 + cq;
        float b0 = __ldg(B3 + col), b1 = __ldg(B3 + col + 1);
        float v0 = fmaxf(fmaxf(acc[0][nb][0], acc[0][nb][2]),
                         fmaxf(acc[1][nb][0], acc[1][nb][2])) + b0;
        float v1 = fmaxf(fmaxf(acc[0][nb][1], acc[0][nb][3]),
                         fmaxf(acc[1][nb][1], acc[1][nb][3])) + b1;
        v0 = fmaxf(v0, 0.f); v1 = fmaxf(v1, 0.f);
#pragma unroll
        for (int off = 4; off <= 16; off <<= 1) {
            v0 = fmaxf(v0, __shfl_xor_sync(0xffffffffu, v0, off));
            v1 = fmaxf(v1, __shfl_xor_sync(0xffffffffu, v1, off));
        }
        if (lane < 4) {
            out[obase + col] = v0;
            out[obase + col + 1] = v1;
        }
    }
}

__global__ void __launch_bounds__(256, 2) mlp_kernel(
    const float* __restrict__ fea,
    const float* __restrict__ W1, const float* __restrict__ B1,
    const float* __restrict__ W2, const float* __restrict__ B2,
    const float* __restrict__ W3, const float* __restrict__ B3,
    float* __restrict__ out)
{
    extern __shared__ char smp[];
    uint32_t sb = smem_u32(smp);
    int tid = threadIdx.x, wid = tid >> 5;
    int b = blockIdx.y, s0 = blockIdx.x * 4;
    int cent = wid >> 1, nhalf = wid & 1;
    int rowBase = cent * 32;

    if (tid < 128) {
        int c = tid >> 5, g = tid & 31, s = s0 + c;
        int far = g_fps[b][s];
        int idx = g_grp[b][s][g];
        float f[80];
        f[0] = g_xs[b][idx] - g_xs[b][far];
        f[1] = g_ys[b][idx] - g_ys[b][far];
        f[2] = g_zs[b][idx] - g_zs[b][far];
        const float4* fr = (const float4*)(fea + ((size_t)b * NPTS + idx) * FDIM);
#pragma unroll
        for (int q = 0; q < 16; q++) {
            float4 v = __ldg(fr + q);
            f[3 + 4 * q + 0] = v.x; f[3 + 4 * q + 1] = v.y;
            f[3 + 4 * q + 2] = v.z; f[3 + 4 * q + 3] = v.w;
        }
#pragma unroll
        for (int q = 67; q < 80; q++) f[q] = 0.f;
#pragma unroll
        for (int q = 0; q < 40; q++) storeA(smp, tid, 2 * q, f[2 * q], f[2 * q + 1]);
    } else {
        stageW<67, 64, 64, 80, 88>(smp, W1, 0, tid - 128, 128);
    }
    __syncthreads();

    {
        float acc[2][4][4];
        warp_gemm<4, 5, 88>(sb, rowBase, nhalf * 32, acc);
        __syncthreads();
        epi_store<4>(smp, rowBase, nhalf * 32, B1, acc);
        stageW<64, 128, 128, 64, 72>(smp, W2, 0, tid, 256);
        __syncthreads();
    }

    {
        float acc[2][8][4];
        warp_gemm<8, 4, 72>(sb, rowBase, nhalf * 64, acc);
        __syncthreads();
        epi_store<8>(smp, rowBase, nhalf * 64, B2, acc);
        stageW<128, 64, 256, 128, 136>(smp, W3, 0, tid, 256);
        __syncthreads();
    }

    size_t obase = (size_t)BATCH * NSAMP * 3 +
                   ((size_t)(b * NSAMP + s0 + cent)) * 256;
    {
        float acc[2][4][4];
        warp_gemm<4, 8, 136>(sb, rowBase, nhalf * 32, acc);
        epi_max(nhalf * 32, B3, out, obase, acc);
        __syncthreads();
        stageW<128, 64, 256, 128, 136>(smp, W3, 64, tid, 256);
        __syncthreads();
        warp_gemm<4, 8, 136>(sb, rowBase, nhalf * 32, acc);
        epi_max(64 + nhalf * 32, B3, out, obase, acc);
        __syncthreads();
        stageW<128, 64, 256, 128, 136>(smp, W3, 128, tid, 256);
        __syncthreads();
        warp_gemm<4, 8, 136>(sb, rowBase, nhalf * 32, acc);
        epi_max(128 + nhalf * 32, B3, out, obase, acc);
        __syncthreads();
        stageW<128, 64, 256, 128, 136>(smp, W3, 192, tid, 256);
        __syncthreads();
        warp_gemm<4, 8, 136>(sb, rowBase, nhalf * 32, acc);
        epi_max(192 + nhalf * 32, B3, out, obase, acc);
    }
}

// ---------------- launcher ----------------
extern "C" void kernel_launch(void* const* d_in, const int* in_sizes, int n_in,
                              void* d_out, int out_size) {
    (void)in_sizes; (void)n_in; (void)out_size;
    const float* xyz = (const float*)d_in[0];
    const float* fea = (const float*)d_in[1];
    const float* W1  = (const float*)d_in[2];
    const float* B1  = (const float*)d_in[3];
    const float* W2  = (const float*)d_in[4];
    const float* B2  = (const float*)d_in[5];
    const float* W3  = (const float*)d_in[6];
    const float* B3  = (const float*)d_in[7];
    float* out = (float*)d_out;

    cudaFuncSetAttribute(mlp_kernel, cudaFuncAttributeMaxDynamicSharedMemorySize,
                         SMEM_TOT);
    cudaFuncSetAttribute(fps_kernel, cudaFuncAttributeMaxDynamicSharedMemorySize,
                         3 * NPTS * 4);

    prep_kernel<<<(BATCH * NPTS + 255) / 256, 256>>>(xyz);
    fps_kernel<<<BATCH, 1024, 3 * NPTS * 4>>>(out);
    ballq_kernel<<<BATCH * NSAMP / 8, 256>>>();
    dim3 grid(NSAMP / 4, BATCH);
    mlp_kernel<<<grid, 256, SMEM_TOT>>>(fea, W1, B1, W2, B2, W3, B3, out);
}

// round 10
// speedup vs baseline: 2.0647x; 1.2834x over previous
#include <cuda_runtime.h>
#include <cuda_bf16.h>
#include <cstdint>
#include <cstddef>

#define BATCH 16
#define NPTS  8192
#define NSAMP 1024
#define NGRP  32
#define FDIM  64

// ---------------- device scratch ----------------
__device__ float g_xs[BATCH][NPTS];
__device__ float g_ys[BATCH][NPTS];
__device__ float g_zs[BATCH][NPTS];
__device__ float g_ss[BATCH][NPTS];
__device__ int   g_fps[BATCH][NSAMP];
__device__ int   g_grp[BATCH][NSAMP][NGRP];
__device__ int   g_prog[BATCH];          // centroids published per batch

// reset progress flags each replay (graph-captured, runs before mega kernel)
__global__ void init_kernel() {
    if (threadIdx.x < BATCH) g_prog[threadIdx.x] = 0;
}

// =====================================================================
// shared helpers (mlp)
// SMEM: A hi [256][136]bf16 @0 (69632), A lo @69632,
//       W hi @139264 (<=18432), W lo @157696 (<=18432).  total 176128
// =====================================================================
#define LDA       136
#define ABUF_HI   0
#define ABUF_LO   69632
#define WBUF_HI   139264
#define WBUF_LO   157696
#define SMEM_TOT  176128

static __device__ __forceinline__ uint32_t smem_u32(const void* p) {
    uint32_t a;
    asm("{ .reg .u64 t; cvta.to.shared.u64 t, %1; cvt.u32.u64 %0, t; }"
        : "=r"(a) : "l"(p));
    return a;
}
static __device__ __forceinline__ void ldm_x4(uint32_t* r, uint32_t addr) {
    asm volatile("ldmatrix.sync.aligned.m8n8.x4.shared.b16 {%0,%1,%2,%3}, [%4];"
                 : "=r"(r[0]), "=r"(r[1]), "=r"(r[2]), "=r"(r[3]) : "r"(addr));
}
static __device__ __forceinline__ void mma_bf16(float* c, const uint32_t* a,
                                                uint32_t b0, uint32_t b1) {
    asm volatile(
        "mma.sync.aligned.m16n8k16.row.col.f32.bf16.bf16.f32 "
        "{%0,%1,%2,%3}, {%4,%5,%6,%7}, {%8,%9}, {%0,%1,%2,%3};"
        : "+f"(c[0]), "+f"(c[1]), "+f"(c[2]), "+f"(c[3])
        : "r"(a[0]), "r"(a[1]), "r"(a[2]), "r"(a[3]), "r"(b0), "r"(b1));
}

static __device__ __forceinline__ void split2(float a, float b,
                                              unsigned& hi, unsigned& lo) {
    __nv_bfloat16 ha = __float2bfloat16(a), hb = __float2bfloat16(b);
    float ra = a - __bfloat162float(ha), rb = b - __bfloat162float(hb);
    __nv_bfloat16 la = __float2bfloat16(ra), lb = __float2bfloat16(rb);
    hi = (unsigned)__bfloat16_as_ushort(ha) | ((unsigned)__bfloat16_as_ushort(hb) << 16);
    lo = (unsigned)__bfloat16_as_ushort(la) | ((unsigned)__bfloat16_as_ushort(lb) << 16);
}
static __device__ __forceinline__ void storeA(char* smp, int row, int col,
                                              float a, float b) {
    unsigned h, l;
    split2(a, b, h, l);
    int off = (row * LDA + col) * 2;
    *(unsigned*)(smp + ABUF_HI + off) = h;
    *(unsigned*)(smp + ABUF_LO + off) = l;
}
template <int K, int N, int LDSRC, int KPAD, int LDWS>
static __device__ __forceinline__ void stageW(char* smp, const float* W, int srcOff,
                                              int tid0, int nthr) {
    for (int idx = tid0; idx < KPAD * N; idx += nthr) {
        int k = idx / N, n = idx - k * N;
        float w = (k < K) ? __ldg(W + k * LDSRC + srcOff + n) : 0.f;
        __nv_bfloat16 h = __float2bfloat16(w);
        float rr = w - __bfloat162float(h);
        __nv_bfloat16 l = __float2bfloat16(rr);
        int off = (n * LDWS + k) * 2;
        *(__nv_bfloat16*)(smp + WBUF_HI + off) = h;
        *(__nv_bfloat16*)(smp + WBUF_LO + off) = l;
    }
}

template <int NBLK, int KSTEPS, int LDWS>
static __device__ __forceinline__ void warp_gemm(uint32_t sb, int rowBase, int nOff,
                                                 float (&acc)[2][NBLK][4]) {
    int lane = threadIdx.x & 31;
#pragma unroll
    for (int m = 0; m < 2; m++)
#pragma unroll
        for (int nb = 0; nb < NBLK; nb++)
#pragma unroll
            for (int i = 0; i < 4; i++) acc[m][nb][i] = 0.f;

    int arow = lane & 15;
    int acolo = (lane >> 4) << 3;
    int bRow = nOff + ((lane >> 4) & 1) * 8 + (lane & 7);
    int bK = lane & 8;

#pragma unroll
    for (int k = 0; k < KSTEPS; k++) {
        int k0 = k << 4;
        uint32_t ah[2][4], al[2][4];
#pragma unroll
        for (int m = 0; m < 2; m++) {
            uint32_t ao = (uint32_t)(((rowBase + m * 16 + arow) * LDA + k0 + acolo) * 2);
            ldm_x4(ah[m], sb + ABUF_HI + ao);
            ldm_x4(al[m], sb + ABUF_LO + ao);
        }
#pragma unroll
        for (int p = 0; p < NBLK / 2; p++) {
            uint32_t wo = (uint32_t)(((bRow + p * 16) * LDWS + k0 + bK) * 2);
            uint32_t bh[4], bl[4];
            ldm_x4(bh, sb + WBUF_HI + wo);
            ldm_x4(bl, sb + WBUF_LO + wo);
#pragma unroll
            for (int m = 0; m < 2; m++) {
                mma_bf16(acc[m][2 * p],     ah[m], bh[0], bh[1]);
                mma_bf16(acc[m][2 * p],     ah[m], bl[0], bl[1]);
                mma_bf16(acc[m][2 * p],     al[m], bh[0], bh[1]);
                mma_bf16(acc[m][2 * p + 1], ah[m], bh[2], bh[3]);
                mma_bf16(acc[m][2 * p + 1], ah[m], bl[2], bl[3]);
                mma_bf16(acc[m][2 * p + 1], al[m], bh[2], bh[3]);
            }
        }
    }
}

template <int NBLK>
static __device__ __forceinline__ void epi_store(char* smp, int rowBase, int colBase,
                                                 const float* __restrict__ bias,
                                                 float (&acc)[2][NBLK][4]) {
    int lane = threadIdx.x & 31;
    int cq = (lane & 3) * 2;
    int rq = lane >> 2;
#pragma unroll
    for (int nb = 0; nb < NBLK; nb++) {
        int col = colBase + nb * 8 + cq;
        float b0 = __ldg(bias + col), b1 = __ldg(bias + col + 1);
#pragma unroll
        for (int m = 0; m < 2; m++) {
            int row = rowBase + m * 16 + rq;
            float v0 = fmaxf(acc[m][nb][0] + b0, 0.f);
            float v1 = fmaxf(acc[m][nb][1] + b1, 0.f);
            float v2 = fmaxf(acc[m][nb][2] + b0, 0.f);
            float v3 = fmaxf(acc[m][nb][3] + b1, 0.f);
            storeA(smp, row, col, v0, v1);
            storeA(smp, row + 8, col, v2, v3);
        }
    }
}

static __device__ __forceinline__ void epi_max(int gColBase, const float* __restrict__ B3,
                                               float* __restrict__ out, size_t obase,
                                               float (&acc)[2][4][4]) {
    int lane = threadIdx.x & 31;
    int cq = (lane & 3) * 2;
#pragma unroll
    for (int nb = 0; nb < 4; nb++) {
        int col = gColBase + nb * 8 + cq;
        float b0 = __ldg(B3 + col), b1 = __ldg(B3 + col + 1);
        float v0 = fmaxf(fmaxf(acc[0][nb][0], acc[0][nb][2]),
                         fmaxf(acc[1][nb][0], acc[1][nb][2])) + b0;
        float v1 = fmaxf(fmaxf(acc[0][nb][1], acc[0][nb][3]),
                         fmaxf(acc[1][nb][1], acc[1][nb][3])) + b1;
        v0 = fmaxf(v0, 0.f); v1 = fmaxf(v1, 0.f);
#pragma unroll
        for (int off = 4; off <= 16; off <<= 1) {
            v0 = fmaxf(v0, __shfl_xor_sync(0xffffffffu, v0, off));
            v1 = fmaxf(v1, __shfl_xor_sync(0xffffffffu, v1, off));
        }
        if (lane < 4) {
            out[obase + col] = v0;
            out[obase + col + 1] = v1;
        }
    }
}

// =====================================================================
// mega kernel: blocks 0..15 = FPS producer (one batch each, 512 thr,
// 16 pts/thread, prep fused); blocks 16.. = ballq+gather+MLP consumer
// (8 centroids, 16 warps = 8 warp-pairs), gated on g_prog[b].
// =====================================================================
__global__ void __launch_bounds__(512, 1) mega_kernel(
    const float* __restrict__ xyz, const float* __restrict__ fea,
    const float* __restrict__ W1, const float* __restrict__ B1,
    const float* __restrict__ W2, const float* __restrict__ B2,
    const float* __restrict__ W3, const float* __restrict__ B3,
    float* __restrict__ out)
{
    extern __shared__ char smp[];

    if (blockIdx.x < BATCH) {
        // ================= FPS role =================
        float* sx = (float*)smp;
        float* sy = sx + NPTS;
        float* sz = sy + NPTS;
        __shared__ uint2 s_wk[2][16];

        int b = blockIdx.x, t = threadIdx.x;
        int lane = t & 31, warp = t >> 5;

        float px[16], py[16], pz[16], dist[16];
#pragma unroll
        for (int j = 0; j < 16; j++) {
            int p = t + 512 * j;
            const float* src = xyz + ((size_t)b * NPTS + p) * 3;
            float x = src[0], y = src[1], z = src[2];
            px[j] = x; py[j] = y; pz[j] = z; dist[j] = 1e10f;
            sx[p] = x; sy[p] = y; sz[p] = z;
            g_xs[b][p] = x; g_ys[b][p] = y; g_zs[b][p] = z;
            g_ss[b][p] = __fmaf_rn(z, z, __fmaf_rn(y, y, __fmul_rn(x, x)));
        }
        __syncthreads();

        int far = 0;
        for (int k = 0; k < NSAMP; k++) {
            if (t == 0) {
                g_fps[b][k] = far;
                size_t o = ((size_t)b * NSAMP + k) * 3;
                out[o + 0] = sx[far];
                out[o + 1] = sy[far];
                out[o + 2] = sz[far];
            }
            float cx = sx[far], cy = sy[far], cz = sz[far];

            unsigned bd = 0u;
            int bidx = 0;
#pragma unroll
            for (int j = 0; j < 16; j++) {
                float dx = __fsub_rn(px[j], cx);
                float dy = __fsub_rn(py[j], cy);
                float dz = __fsub_rn(pz[j], cz);
                float d = __fmaf_rn(dz, dz, __fmaf_rn(dy, dy, __fmul_rn(dx, dx)));
                float dm = fminf(dist[j], d);
                dist[j] = dm;
                unsigned db = __float_as_uint(dm);   // dm>=0: u32 order == float
                if (j == 0) { bd = db; bidx = t; }
                else if (db > bd) { bd = db; bidx = t + 512 * j; }  // strict > keeps lowest idx
            }
            unsigned wmax = __reduce_max_sync(0xffffffffu, bd);
            unsigned cand = (bd == wmax) ? (unsigned)bidx : 0xffffffffu;
            unsigned widx = __reduce_min_sync(0xffffffffu, cand);
            if (lane == 0) s_wk[k & 1][warp] = make_uint2(wmax, widx);
            __syncthreads();
            uint2 v = (lane < 16) ? s_wk[k & 1][lane] : make_uint2(0u, 0xffffffffu);
            unsigned m2 = __reduce_max_sync(0xffffffffu, v.x);
            unsigned c2 = (v.x == m2) ? v.y : 0xffffffffu;
            far = (int)__reduce_min_sync(0xffffffffu, c2);

            if (t == 0 && ((k + 1) & 7) == 0) {
                __threadfence();                       // publish g_fps/out/init writes
                *(volatile int*)&g_prog[b] = k + 1;
            }
        }
        return;
    }

    // ================= MLP role =================
    uint32_t sb = smem_u32(smp);
    int tid = threadIdx.x, wid = tid >> 5, lane = tid & 31;
    int mlpIdx = blockIdx.x - BATCH;
    int b = mlpIdx & 15;                 // batch-minor: early blocks want early centroids
    int s0 = (mlpIdx >> 4) * 8;
    int cent = wid >> 1, nhalf = wid & 1;
    int rowBase = cent * 32;

    // gate on producer
    if (tid == 0) {
        while (*(volatile int*)&g_prog[b] < s0 + 8) __nanosleep(256);
        __threadfence();
    }
    __syncthreads();

    // phase A: warps 0..7 ball-query one centroid each; warps 8..15 stage W1
    if (wid < 8) {
        int s = s0 + wid;
        int far = __ldcg(&g_fps[b][s]);          // L2-scope: progressive data
        float ax = g_xs[b][far], ay = g_ys[b][far], az = g_zs[b][far];
        float sa = __fmaf_rn(az, az, __fmaf_rn(ay, ay, __fmul_rn(ax, ax)));
        const float RR = 0.04f;
        int filled = 0;
        for (int base = 0; base < NPTS; base += 32) {
            int n = base + lane;
            float bx = g_xs[b][n], by = g_ys[b][n], bz = g_zs[b][n], sbq = g_ss[b][n];
            float dot = __fmaf_rn(az, bz, __fmaf_rn(ay, by, __fmul_rn(ax, bx)));
            float sq = __fsub_rn(__fadd_rn(sa, sbq), __fmul_rn(2.0f, dot));
            bool inr = !(sq > RR);
            unsigned m = __ballot_sync(0xffffffffu, inr);
            int pos = filled + __popc(m & ((1u << lane) - 1u));
            if (inr && pos < NGRP) g_grp[b][s][pos] = n;
            filled += __popc(m);
            if (filled >= NGRP) break;
        }
        if (filled < NGRP) {
            __syncwarp();
            int first = g_grp[b][s][0];
            int j = filled + lane;
            if (j < NGRP) g_grp[b][s][j] = first;
        }
    } else {
        stageW<67, 64, 64, 80, 88>(smp, W1, 0, tid - 256, 256);
    }
    __syncthreads();

    // phase B: gather feats (256 rows, one per thread 0..255)
    if (tid < 256) {
        int c = tid >> 5, g = tid & 31, s = s0 + c;
        int far = __ldcg(&g_fps[b][s]);
        int idx = g_grp[b][s][g];
        float f[80];
        f[0] = g_xs[b][idx] - g_xs[b][far];
        f[1] = g_ys[b][idx] - g_ys[b][far];
        f[2] = g_zs[b][idx] - g_zs[b][far];
        const float4* fr = (const float4*)(fea + ((size_t)b * NPTS + idx) * FDIM);
#pragma unroll
        for (int q = 0; q < 16; q++) {
            float4 v = __ldg(fr + q);
            f[3 + 4 * q + 0] = v.x; f[3 + 4 * q + 1] = v.y;
            f[3 + 4 * q + 2] = v.z; f[3 + 4 * q + 3] = v.w;
        }
#pragma unroll
        for (int q = 67; q < 80; q++) f[q] = 0.f;
#pragma unroll
        for (int q = 0; q < 40; q++) storeA(smp, tid, 2 * q, f[2 * q], f[2 * q + 1]);
    }
    __syncthreads();

    // L1: [256x80] @ [80x64]
    {
        float acc[2][4][4];
        warp_gemm<4, 5, 88>(sb, rowBase, nhalf * 32, acc);
        __syncthreads();
        epi_store<4>(smp, rowBase, nhalf * 32, B1, acc);
        stageW<64, 128, 128, 64, 72>(smp, W2, 0, tid, 512);
        __syncthreads();
    }
    // L2: [256x64] @ [64x128]
    {
        float acc[2][8][4];
        warp_gemm<8, 4, 72>(sb, rowBase, nhalf * 64, acc);
        __syncthreads();
        epi_store<8>(smp, rowBase, nhalf * 64, B2, acc);
        stageW<128, 64, 256, 128, 136>(smp, W3, 0, tid, 512);
        __syncthreads();
    }
    // L3: [256x128] @ [128x256] in four 64-col chunks + maxpool
    size_t obase = (size_t)BATCH * NSAMP * 3 +
                   ((size_t)(b * NSAMP + s0 + cent)) * 256;
    {
        float acc[2][4][4];
        warp_gemm<4, 8, 136>(sb, rowBase, nhalf * 32, acc);
        epi_max(nhalf * 32, B3, out, obase, acc);
        __syncthreads();
        stageW<128, 64, 256, 128, 136>(smp, W3, 64, tid, 512);
        __syncthreads();
        warp_gemm<4, 8, 136>(sb, rowBase, nhalf * 32, acc);
        epi_max(64 + nhalf * 32, B3, out, obase, acc);
        __syncthreads();
        stageW<128, 64, 256, 128, 136>(smp, W3, 128, tid, 512);
        __syncthreads();
        warp_gemm<4, 8, 136>(sb, rowBase, nhalf * 32, acc);
        epi_max(128 + nhalf * 32, B3, out, obase, acc);
        __syncthreads();
        stageW<128, 64, 256, 128, 136>(smp, W3, 192, tid, 512);
        __syncthreads();
        warp_gemm<4, 8, 136>(sb, rowBase, nhalf * 32, acc);
        epi_max(192 + nhalf * 32, B3, out, obase, acc);
    }
}

// ---------------- launcher ----------------
extern "C" void kernel_launch(void* const* d_in, const int* in_sizes, int n_in,
                              void* d_out, int out_size) {
    (void)in_sizes; (void)n_in; (void)out_size;
    const float* xyz = (const float*)d_in[0];
    const float* fea = (const float*)d_in[1];
    const float* W1  = (const float*)d_in[2];
    const float* B1  = (const float*)d_in[3];
    const float* W2  = (const float*)d_in[4];
    const float* B2  = (const float*)d_in[5];
    const float* W3  = (const float*)d_in[6];
    const float* B3  = (const float*)d_in[7];
    float* out = (float*)d_out;

    cudaFuncSetAttribute(mega_kernel, cudaFuncAttributeMaxDynamicSharedMemorySize,
                         SMEM_TOT);

    init_kernel<<<1, 32>>>();
    int grid = BATCH + BATCH * (NSAMP / 8);   // 16 fps + 2048 mlp = 2064
    mega_kernel<<<grid, 512, SMEM_TOT>>>(xyz, fea, W1, B1, W2, B2, W3, B3, out);
}

// round 12
// speedup vs baseline: 2.3368x; 1.1318x over previous
#include <cuda_runtime.h>
#include <cuda_bf16.h>
#include <cstdint>
#include <cstddef>

#define BATCH 16
#define NPTS  8192
#define NSAMP 1024
#define NGRP  32
#define FDIM  64

// ---------------- device scratch ----------------
__device__ float g_xs[BATCH][NPTS];
__device__ float g_ys[BATCH][NPTS];
__device__ float g_zs[BATCH][NPTS];
__device__ float g_ss[BATCH][NPTS];
__device__ int   g_fps[BATCH][NSAMP];
__device__ int   g_grp[BATCH][NSAMP][NGRP];
__device__ int   g_prog[BATCH];

__global__ void init_kernel() {
    if (threadIdx.x < BATCH) g_prog[threadIdx.x] = 0;
}

// =====================================================================
// SMEM layout (bytes), per MLP block (two independent 256-thread units):
//   unit u A hi  @ u*34816            [128][136] bf16
//   unit u A lo  @ 69632 + u*34816    (lo = hi + 69632)
//   unit u W hi  @ 139264 + u*36864   (<=18432)
//   unit u W lo  @ hi + 18432
// total 212992
// =====================================================================
#define LDA       136
#define ALO_GAP   69632
#define WLO_GAP   18432
#define WREGION   139264
#define SMEM_TOT  212992

static __device__ __forceinline__ uint32_t smem_u32(const void* p) {
    uint32_t a;
    asm("{ .reg .u64 t; cvta.to.shared.u64 t, %1; cvt.u32.u64 %0, t; }"
        : "=r"(a) : "l"(p));
    return a;
}
static __device__ __forceinline__ void ldm_x4(uint32_t* r, uint32_t addr) {
    asm volatile("ldmatrix.sync.aligned.m8n8.x4.shared.b16 {%0,%1,%2,%3}, [%4];"
                 : "=r"(r[0]), "=r"(r[1]), "=r"(r[2]), "=r"(r[3]) : "r"(addr));
}
static __device__ __forceinline__ void mma_bf16(float* c, const uint32_t* a,
                                                uint32_t b0, uint32_t b1) {
    asm volatile(
        "mma.sync.aligned.m16n8k16.row.col.f32.bf16.bf16.f32 "
        "{%0,%1,%2,%3}, {%4,%5,%6,%7}, {%8,%9}, {%0,%1,%2,%3};"
        : "+f"(c[0]), "+f"(c[1]), "+f"(c[2]), "+f"(c[3])
        : "r"(a[0]), "r"(a[1]), "r"(a[2]), "r"(a[3]), "r"(b0), "r"(b1));
}

static __device__ __forceinline__ void split2(float a, float b,
                                              unsigned& hi, unsigned& lo) {
    __nv_bfloat16 ha = __float2bfloat16(a), hb = __float2bfloat16(b);
    float ra = a - __bfloat162float(ha), rb = b - __bfloat162float(hb);
    __nv_bfloat16 la = __float2bfloat16(ra), lb = __float2bfloat16(rb);
    hi = (unsigned)__bfloat16_as_ushort(ha) | ((unsigned)__bfloat16_as_ushort(hb) << 16);
    lo = (unsigned)__bfloat16_as_ushort(la) | ((unsigned)__bfloat16_as_ushort(lb) << 16);
}
static __device__ __forceinline__ void storeA(char* aBase, int row, int col,
                                              float a, float b) {
    unsigned h, l;
    split2(a, b, h, l);
    int off = (row * LDA + col) * 2;
    *(unsigned*)(aBase + off) = h;
    *(unsigned*)(aBase + ALO_GAP + off) = l;
}
template <int K, int N, int LDSRC, int KPAD, int LDWS>
static __device__ __forceinline__ void stageW(char* wBase, const float* W, int srcOff,
                                              int tid0, int nthr) {
    for (int idx = tid0; idx < KPAD * N; idx += nthr) {
        int k = idx / N, n = idx - k * N;
        float w = (k < K) ? __ldg(W + k * LDSRC + srcOff + n) : 0.f;
        __nv_bfloat16 h = __float2bfloat16(w);
        float rr = w - __bfloat162float(h);
        __nv_bfloat16 l = __float2bfloat16(rr);
        int off = (n * LDWS + k) * 2;
        *(__nv_bfloat16*)(wBase + off) = h;
        *(__nv_bfloat16*)(wBase + WLO_GAP + off) = l;
    }
}

template <int NBLK, int KSTEPS, int LDWS>
static __device__ __forceinline__ void warp_gemm(uint32_t aB, uint32_t wB,
                                                 int rowBase, int nOff,
                                                 float (&acc)[2][NBLK][4]) {
    int lane = threadIdx.x & 31;
#pragma unroll
    for (int m = 0; m < 2; m++)
#pragma unroll
        for (int nb = 0; nb < NBLK; nb++)
#pragma unroll
            for (int i = 0; i < 4; i++) acc[m][nb][i] = 0.f;

    int arow = lane & 15;
    int acolo = (lane >> 4) << 3;
    int bRow = nOff + ((lane >> 4) & 1) * 8 + (lane & 7);
    int bK = lane & 8;

#pragma unroll
    for (int k = 0; k < KSTEPS; k++) {
        int k0 = k << 4;
        uint32_t ah[2][4], al[2][4];
#pragma unroll
        for (int m = 0; m < 2; m++) {
            uint32_t ao = (uint32_t)(((rowBase + m * 16 + arow) * LDA + k0 + acolo) * 2);
            ldm_x4(ah[m], aB + ao);
            ldm_x4(al[m], aB + ALO_GAP + ao);
        }
#pragma unroll
        for (int p = 0; p < NBLK / 2; p++) {
            uint32_t wo = (uint32_t)(((bRow + p * 16) * LDWS + k0 + bK) * 2);
            uint32_t bh[4], bl[4];
            ldm_x4(bh, wB + wo);
            ldm_x4(bl, wB + WLO_GAP + wo);
#pragma unroll
            for (int m = 0; m < 2; m++) {
                mma_bf16(acc[m][2 * p],     ah[m], bh[0], bh[1]);
                mma_bf16(acc[m][2 * p],     ah[m], bl[0], bl[1]);
                mma_bf16(acc[m][2 * p],     al[m], bh[0], bh[1]);
                mma_bf16(acc[m][2 * p + 1], ah[m], bh[2], bh[3]);
                mma_bf16(acc[m][2 * p + 1], ah[m], bl[2], bl[3]);
                mma_bf16(acc[m][2 * p + 1], al[m], bh[2], bh[3]);
            }
        }
    }
}

template <int NBLK>
static __device__ __forceinline__ void epi_store(char* aBase, int rowBase, int colBase,
                                                 const float* __restrict__ bias,
                                                 float (&acc)[2][NBLK][4]) {
    int lane = threadIdx.x & 31;
    int cq = (lane & 3) * 2;
    int rq = lane >> 2;
#pragma unroll
    for (int nb = 0; nb < NBLK; nb++) {
        int col = colBase + nb * 8 + cq;
        float b0 = __ldg(bias + col), b1 = __ldg(bias + col + 1);
#pragma unroll
        for (int m = 0; m < 2; m++) {
            int row = rowBase + m * 16 + rq;
            float v0 = fmaxf(acc[m][nb][0] + b0, 0.f);
            float v1 = fmaxf(acc[m][nb][1] + b1, 0.f);
            float v2 = fmaxf(acc[m][nb][2] + b0, 0.f);
            float v3 = fmaxf(acc[m][nb][3] + b1, 0.f);
            storeA(aBase, row, col, v0, v1);
            storeA(aBase, row + 8, col, v2, v3);
        }
    }
}

static __device__ __forceinline__ void epi_max(int gColBase, const float* __restrict__ B3,
                                               float* __restrict__ out, size_t obase,
                                               float (&acc)[2][4][4]) {
    int lane = threadIdx.x & 31;
    int cq = (lane & 3) * 2;
#pragma unroll
    for (int nb = 0; nb < 4; nb++) {
        int col = gColBase + nb * 8 + cq;
        float b0 = __ldg(B3 + col), b1 = __ldg(B3 + col + 1);
        float v0 = fmaxf(fmaxf(acc[0][nb][0], acc[0][nb][2]),
                         fmaxf(acc[1][nb][0], acc[1][nb][2])) + b0;
        float v1 = fmaxf(fmaxf(acc[0][nb][1], acc[0][nb][3]),
                         fmaxf(acc[1][nb][1], acc[1][nb][3])) + b1;
        v0 = fmaxf(v0, 0.f); v1 = fmaxf(v1, 0.f);
#pragma unroll
        for (int off = 4; off <= 16; off <<= 1) {
            v0 = fmaxf(v0, __shfl_xor_sync(0xffffffffu, v0, off));
            v1 = fmaxf(v1, __shfl_xor_sync(0xffffffffu, v1, off));
        }
        if (lane < 4) {
            out[obase + col] = v0;
            out[obase + col + 1] = v1;
        }
    }
}

// =====================================================================
// mega kernel: blocks 0..15 = FPS producer; blocks 16.. = two independent
// 256-thread MLP units (4 centroids each), phase-overlapped via named bars.
// =====================================================================
__global__ void __launch_bounds__(512, 1) mega_kernel(
    const float* __restrict__ xyz, const float* __restrict__ fea,
    const float* __restrict__ W1, const float* __restrict__ B1,
    const float* __restrict__ W2, const float* __restrict__ B2,
    const float* __restrict__ W3, const float* __restrict__ B3,
    float* __restrict__ out)
{
    extern __shared__ char smp[];

    if (blockIdx.x < BATCH) {
        // ================= FPS role =================
        float* sx = (float*)smp;
        float* sy = sx + NPTS;
        float* sz = sy + NPTS;
        __shared__ uint2 s_wk[2][16];

        int b = blockIdx.x, t = threadIdx.x;
        int lane = t & 31, warp = t >> 5;

        float px[16], py[16], pz[16], dist[16];
#pragma unroll
        for (int j = 0; j < 16; j++) {
            int p = t + 512 * j;
            const float* src = xyz + ((size_t)b * NPTS + p) * 3;
            float x = src[0], y = src[1], z = src[2];
            px[j] = x; py[j] = y; pz[j] = z; dist[j] = 1e10f;
            sx[p] = x; sy[p] = y; sz[p] = z;
            g_xs[b][p] = x; g_ys[b][p] = y; g_zs[b][p] = z;
            g_ss[b][p] = __fmaf_rn(z, z, __fmaf_rn(y, y, __fmul_rn(x, x)));
        }
        __threadfence();          // publish point arrays before first prog post
        __syncthreads();

        int far = 0;
        for (int k = 0; k < NSAMP; k++) {
            if (t == 0) g_fps[b][k] = far;
            float cx = sx[far], cy = sy[far], cz = sz[far];

            unsigned bd = 0u;
            int bidx = 0;
#pragma unroll
            for (int j = 0; j < 16; j++) {
                float dx = __fsub_rn(px[j], cx);
                float dy = __fsub_rn(py[j], cy);
                float dz = __fsub_rn(pz[j], cz);
                float d = __fmaf_rn(dz, dz, __fmaf_rn(dy, dy, __fmul_rn(dx, dx)));
                float dm = fminf(dist[j], d);
                dist[j] = dm;
                unsigned db = __float_as_uint(dm);
                if (j == 0) { bd = db; bidx = t; }
                else if (db > bd) { bd = db; bidx = t + 512 * j; }
            }
            unsigned wmax = __reduce_max_sync(0xffffffffu, bd);
            unsigned cand = (bd == wmax) ? (unsigned)bidx : 0xffffffffu;
            unsigned widx = __reduce_min_sync(0xffffffffu, cand);
            if (lane == 0) s_wk[k & 1][warp] = make_uint2(wmax, widx);
            __syncthreads();
            uint2 v = (lane < 16) ? s_wk[k & 1][lane] : make_uint2(0u, 0xffffffffu);
            unsigned m2 = __reduce_max_sync(0xffffffffu, v.x);
            unsigned c2 = (v.x == m2) ? v.y : 0xffffffffu;
            far = (int)__reduce_min_sync(0xffffffffu, c2);

            if (t == 0 && ((k + 1) & 7) == 0) {
                __threadfence();
                *(volatile int*)&g_prog[b] = k + 1;
            }
        }
        // write sampled_xyz after the serial loop (off critical path)
        __syncthreads();
        for (int k = t; k < NSAMP; k += 512) {
            int f = g_fps[b][k];
            size_t o = ((size_t)b * NSAMP + k) * 3;
            out[o + 0] = sx[f];
            out[o + 1] = sy[f];
            out[o + 2] = sz[f];
        }
        return;
    }

    // ================= MLP role: two independent units =================
    uint32_t sb = smem_u32(smp);
    int tid = threadIdx.x, lane = tid & 31;
    int unit = tid >> 8;
    int utid = tid & 255;
    int uwid = utid >> 5;
    int mlpIdx = blockIdx.x - BATCH;
    int b = mlpIdx & 15;
    int s0 = (mlpIdx >> 4) * 8 + unit * 4;
    int cent = uwid >> 1, nhalf = uwid & 1;
    int rowBase = cent * 32;

    char* aBase = smp + unit * 34816;
    char* wBase = smp + WREGION + unit * 36864;
    uint32_t aB = sb + unit * 34816;
    uint32_t wB = sb + WREGION + unit * 36864;
    int barid = 1 + unit;
#define UBAR() asm volatile("bar.sync %0, 256;" :: "r"(barid) : "memory")

    // gate on producer (per unit)
    if (utid == 0) {
        while (*(volatile int*)&g_prog[b] < s0 + 4) __nanosleep(128);
        __threadfence();
    }
    UBAR();

    // phase A: warps 0-3 ball-query || warps 4-7 stage W1
    if (uwid < 4) {
        int s = s0 + uwid;
        int far = __ldcg(&g_fps[b][s]);
        float ax = g_xs[b][far], ay = g_ys[b][far], az = g_zs[b][far];
        float sa = __fmaf_rn(az, az, __fmaf_rn(ay, ay, __fmul_rn(ax, ax)));
        const float RR = 0.04f;
        int filled = 0;
        for (int base = 0; base < NPTS; base += 32) {
            int n = base + lane;
            float bx = g_xs[b][n], by = g_ys[b][n], bz = g_zs[b][n], sbq = g_ss[b][n];
            float dot = __fmaf_rn(az, bz, __fmaf_rn(ay, by, __fmul_rn(ax, bx)));
            float sq = __fsub_rn(__fadd_rn(sa, sbq), __fmul_rn(2.0f, dot));
            bool inr = !(sq > RR);
            unsigned m = __ballot_sync(0xffffffffu, inr);
            int pos = filled + __popc(m & ((1u << lane) - 1u));
            if (inr && pos < NGRP) g_grp[b][s][pos] = n;
            filled += __popc(m);
            if (filled >= NGRP) break;
        }
        if (filled < NGRP) {
            __syncwarp();
            int first = g_grp[b][s][0];
            int j = filled + lane;
            if (j < NGRP) g_grp[b][s][j] = first;
        }
    } else {
        stageW<67, 64, 64, 80, 88>(wBase, W1, 0, utid - 128, 128);
    }
    UBAR();

    // phase B: gather feats (128 rows, threads 0..127 of unit)
    if (utid < 128) {
        int c = utid >> 5, g = utid & 31, s = s0 + c;
        int far = __ldcg(&g_fps[b][s]);
        int idx = g_grp[b][s][g];
        float f[80];
        f[0] = g_xs[b][idx] - g_xs[b][far];
        f[1] = g_ys[b][idx] - g_ys[b][far];
        f[2] = g_zs[b][idx] - g_zs[b][far];
        const float4* fr = (const float4*)(fea + ((size_t)b * NPTS + idx) * FDIM);
#pragma unroll
        for (int q = 0; q < 16; q++) {
            float4 v = __ldg(fr + q);
            f[3 + 4 * q + 0] = v.x; f[3 + 4 * q + 1] = v.y;
            f[3 + 4 * q + 2] = v.z; f[3 + 4 * q + 3] = v.w;
        }
#pragma unroll
        for (int q = 67; q < 80; q++) f[q] = 0.f;
#pragma unroll
        for (int q = 0; q < 40; q++) storeA(aBase, utid, 2 * q, f[2 * q], f[2 * q + 1]);
    }
    UBAR();

    // L1: [128x80] @ [80x64]
    {
        float acc[2][4][4];
        warp_gemm<4, 5, 88>(aB, wB, rowBase, nhalf * 32, acc);
        UBAR();
        epi_store<4>(aBase, rowBase, nhalf * 32, B1, acc);
        stageW<64, 128, 128, 64, 72>(wBase, W2, 0, utid, 256);
        UBAR();
    }
    // L2: [128x64] @ [64x128]
    {
        float acc[2][8][4];
        warp_gemm<8, 4, 72>(aB, wB, rowBase, nhalf * 64, acc);
        UBAR();
        epi_store<8>(aBase, rowBase, nhalf * 64, B2, acc);
        stageW<128, 64, 256, 128, 136>(wBase, W3, 0, utid, 256);
        UBAR();
    }
    // L3: [128x128] @ [128x256] in four 64-col chunks + maxpool
    size_t obase = (size_t)BATCH * NSAMP * 3 +
                   ((size_t)(b * NSAMP + s0 + cent)) * 256;
    {
        float acc[2][4][4];
        warp_gemm<4, 8, 136>(aB, wB, rowBase, nhalf * 32, acc);
        epi_max(nhalf * 32, B3, out, obase, acc);
        UBAR();
        stageW<128, 64, 256, 128, 136>(wBase, W3, 64, utid, 256);
        UBAR();
        warp_gemm<4, 8, 136>(aB, wB, rowBase, nhalf * 32, acc);
        epi_max(64 + nhalf * 32, B3, out, obase, acc);
        UBAR();
        stageW<128, 64, 256, 128, 136>(wBase, W3, 128, utid, 256);
        UBAR();
        warp_gemm<4, 8, 136>(aB, wB, rowBase, nhalf * 32, acc);
        epi_max(128 + nhalf * 32, B3, out, obase, acc);
        UBAR();
        stageW<128, 64, 256, 128, 136>(wBase, W3, 192, utid, 256);
        UBAR();
        warp_gemm<4, 8, 136>(aB, wB, rowBase, nhalf * 32, acc);
        epi_max(192 + nhalf * 32, B3, out, obase, acc);
    }
#undef UBAR
}

// ---------------- launcher ----------------
extern "C" void kernel_launch(void* const* d_in, const int* in_sizes, int n_in,
                              void* d_out, int out_size) {
    (void)in_sizes; (void)n_in; (void)out_size;
    const float* xyz = (const float*)d_in[0];
    const float* fea = (const float*)d_in[1];
    const float* W1  = (const float*)d_in[2];
    const float* B1  = (const float*)d_in[3];
    const float* W2  = (const float*)d_in[4];
    const float* B2  = (const float*)d_in[5];
    const float* W3  = (const float*)d_in[6];
    const float* B3  = (const float*)d_in[7];
    float* out = (float*)d_out;

    cudaFuncSetAttribute(mega_kernel, cudaFuncAttributeMaxDynamicSharedMemorySize,
                         SMEM_TOT);

    init_kernel<<<1, 32>>>();
    int grid = BATCH + BATCH * (NSAMP / 8);   // 16 fps + 2048 mlp = 2064
    mega_kernel<<<grid, 512, SMEM_TOT>>>(xyz, fea, W1, B1, W2, B2, W3, B3, out);
}

// round 13
// speedup vs baseline: 2.6492x; 1.1337x over previous
#include <cuda_runtime.h>
#include <cuda_bf16.h>
#include <cstdint>
#include <cstddef>

#define BATCH 16
#define NPTS  8192
#define NSAMP 1024
#define NGRP  32
#define FDIM  64
#define NCHUNK (BATCH * NSAMP / 4)      // 4096 4-centroid work items

// ---------------- device scratch ----------------
__device__ float g_xs[BATCH][NPTS];
__device__ float g_ys[BATCH][NPTS];
__device__ float g_zs[BATCH][NPTS];
__device__ float g_ss[BATCH][NPTS];
__device__ int   g_fps[BATCH][NSAMP];
__device__ int   g_grp[BATCH][NSAMP][NGRP];
__device__ int   g_prog[BATCH];
__device__ int   g_qhead;

// pre-split weights, already in smem [N][LDWS] bf16 layout ([0]=hi, [1]=lo)
__device__ __align__(16) __nv_bfloat16 g_W1s[2][64 * 88];
__device__ __align__(16) __nv_bfloat16 g_W2s[2][128 * 72];
__device__ __align__(16) __nv_bfloat16 g_W3s[2][256 * 136];

// ---------------- init: reset queue/progress + pre-split weights ----------
__global__ void init_kernel(const float* __restrict__ W1,
                            const float* __restrict__ W2,
                            const float* __restrict__ W3) {
    int nth = gridDim.x * blockDim.x;
    int i = blockIdx.x * blockDim.x + threadIdx.x;
    if (i < BATCH) g_prog[i] = 0;
    if (i == BATCH) g_qhead = 0;
    for (int idx = i; idx < 64 * 88; idx += nth) {
        int n = idx / 88, k = idx - n * 88;
        float w = (k < 67) ? __ldg(W1 + k * 64 + n) : 0.f;
        __nv_bfloat16 h = __float2bfloat16(w);
        __nv_bfloat16 l = __float2bfloat16(w - __bfloat162float(h));
        g_W1s[0][idx] = h; g_W1s[1][idx] = l;
    }
    for (int idx = i; idx < 128 * 72; idx += nth) {
        int n = idx / 72, k = idx - n * 72;
        float w = (k < 64) ? __ldg(W2 + k * 128 + n) : 0.f;
        __nv_bfloat16 h = __float2bfloat16(w);
        __nv_bfloat16 l = __float2bfloat16(w - __bfloat162float(h));
        g_W2s[0][idx] = h; g_W2s[1][idx] = l;
    }
    for (int idx = i; idx < 256 * 136; idx += nth) {
        int n = idx / 136, k = idx - n * 136;
        float w = (k < 128) ? __ldg(W3 + k * 256 + n) : 0.f;
        __nv_bfloat16 h = __float2bfloat16(w);
        __nv_bfloat16 l = __float2bfloat16(w - __bfloat162float(h));
        g_W3s[0][idx] = h; g_W3s[1][idx] = l;
    }
}

// =====================================================================
// SMEM layout (bytes), per MLP block (two independent 256-thread units):
//   [A0hi 34816][A1hi 34816][A0lo 34816][A1lo 34816]
//   [W0hi 18432][W0lo 18432][W1hi 18432][W1lo 18432]   total 212992
// =====================================================================
#define LDA       136
#define ALO_GAP   69632
#define WLO_GAP   18432
#define WREGION   139264
#define SMEM_TOT  212992

static __device__ __forceinline__ uint32_t smem_u32(const void* p) {
    uint32_t a;
    asm("{ .reg .u64 t; cvta.to.shared.u64 t, %1; cvt.u32.u64 %0, t; }"
        : "=r"(a) : "l"(p));
    return a;
}
static __device__ __forceinline__ void ldm_x4(uint32_t* r, uint32_t addr) {
    asm volatile("ldmatrix.sync.aligned.m8n8.x4.shared.b16 {%0,%1,%2,%3}, [%4];"
                 : "=r"(r[0]), "=r"(r[1]), "=r"(r[2]), "=r"(r[3]) : "r"(addr));
}
static __device__ __forceinline__ void mma_bf16(float* c, const uint32_t* a,
                                                uint32_t b0, uint32_t b1) {
    asm volatile(
        "mma.sync.aligned.m16n8k16.row.col.f32.bf16.bf16.f32 "
        "{%0,%1,%2,%3}, {%4,%5,%6,%7}, {%8,%9}, {%0,%1,%2,%3};"
        : "+f"(c[0]), "+f"(c[1]), "+f"(c[2]), "+f"(c[3])
        : "r"(a[0]), "r"(a[1]), "r"(a[2]), "r"(a[3]), "r"(b0), "r"(b1));
}

static __device__ __forceinline__ void split2(float a, float b,
                                              unsigned& hi, unsigned& lo) {
    __nv_bfloat16 ha = __float2bfloat16(a), hb = __float2bfloat16(b);
    float ra = a - __bfloat162float(ha), rb = b - __bfloat162float(hb);
    __nv_bfloat16 la = __float2bfloat16(ra), lb = __float2bfloat16(rb);
    hi = (unsigned)__bfloat16_as_ushort(ha) | ((unsigned)__bfloat16_as_ushort(hb) << 16);
    lo = (unsigned)__bfloat16_as_ushort(la) | ((unsigned)__bfloat16_as_ushort(lb) << 16);
}
static __device__ __forceinline__ void storeA(char* aBase, int row, int col,
                                              float a, float b) {
    unsigned h, l;
    split2(a, b, h, l);
    int off = (row * LDA + col) * 2;
    *(unsigned*)(aBase + off) = h;
    *(unsigned*)(aBase + ALO_GAP + off) = l;
}
// pure vector copy: pre-split global weights -> unit W buffer
static __device__ __forceinline__ void copyW(char* dst, const __nv_bfloat16* src,
                                             int bytes, int t0, int nt) {
    const uint4* s = (const uint4*)src;
    uint4* d = (uint4*)dst;
    for (int i = t0; i < bytes / 16; i += nt) d[i] = s[i];
}

template <int NBLK, int KSTEPS, int LDWS>
static __device__ __forceinline__ void warp_gemm(uint32_t aB, uint32_t wB,
                                                 int rowBase, int nOff,
                                                 float (&acc)[2][NBLK][4]) {
    int lane = threadIdx.x & 31;
#pragma unroll
    for (int m = 0; m < 2; m++)
#pragma unroll
        for (int nb = 0; nb < NBLK; nb++)
#pragma unroll
            for (int i = 0; i < 4; i++) acc[m][nb][i] = 0.f;

    int arow = lane & 15;
    int acolo = (lane >> 4) << 3;
    int bRow = nOff + ((lane >> 4) & 1) * 8 + (lane & 7);
    int bK = lane & 8;

#pragma unroll
    for (int k = 0; k < KSTEPS; k++) {
        int k0 = k << 4;
        uint32_t ah[2][4], al[2][4];
#pragma unroll
        for (int m = 0; m < 2; m++) {
            uint32_t ao = (uint32_t)(((rowBase + m * 16 + arow) * LDA + k0 + acolo) * 2);
            ldm_x4(ah[m], aB + ao);
            ldm_x4(al[m], aB + ALO_GAP + ao);
        }
#pragma unroll
        for (int p = 0; p < NBLK / 2; p++) {
            uint32_t wo = (uint32_t)(((bRow + p * 16) * LDWS + k0 + bK) * 2);
            uint32_t bh[4], bl[4];
            ldm_x4(bh, wB + wo);
            ldm_x4(bl, wB + WLO_GAP + wo);
#pragma unroll
            for (int m = 0; m < 2; m++) {
                mma_bf16(acc[m][2 * p],     ah[m], bh[0], bh[1]);
                mma_bf16(acc[m][2 * p],     ah[m], bl[0], bl[1]);
                mma_bf16(acc[m][2 * p],     al[m], bh[0], bh[1]);
                mma_bf16(acc[m][2 * p + 1], ah[m], bh[2], bh[3]);
                mma_bf16(acc[m][2 * p + 1], ah[m], bl[2], bl[3]);
                mma_bf16(acc[m][2 * p + 1], al[m], bh[2], bh[3]);
            }
        }
    }
}

template <int NBLK>
static __device__ __forceinline__ void epi_store(char* aBase, int rowBase, int colBase,
                                                 const float* __restrict__ bias,
                                                 float (&acc)[2][NBLK][4]) {
    int lane = threadIdx.x & 31;
    int cq = (lane & 3) * 2;
    int rq = lane >> 2;
#pragma unroll
    for (int nb = 0; nb < NBLK; nb++) {
        int col = colBase + nb * 8 + cq;
        float b0 = __ldg(bias + col), b1 = __ldg(bias + col + 1);
#pragma unroll
        for (int m = 0; m < 2; m++) {
            int row = rowBase + m * 16 + rq;
            float v0 = fmaxf(acc[m][nb][0] + b0, 0.f);
            float v1 = fmaxf(acc[m][nb][1] + b1, 0.f);
            float v2 = fmaxf(acc[m][nb][2] + b0, 0.f);
            float v3 = fmaxf(acc[m][nb][3] + b1, 0.f);
            storeA(aBase, row, col, v0, v1);
            storeA(aBase, row + 8, col, v2, v3);
        }
    }
}

static __device__ __forceinline__ void epi_max(int gColBase, const float* __restrict__ B3,
                                               float* __restrict__ out, size_t obase,
                                               float (&acc)[2][4][4]) {
    int lane = threadIdx.x & 31;
    int cq = (lane & 3) * 2;
#pragma unroll
    for (int nb = 0; nb < 4; nb++) {
        int col = gColBase + nb * 8 + cq;
        float b0 = __ldg(B3 + col), b1 = __ldg(B3 + col + 1);
        float v0 = fmaxf(fmaxf(acc[0][nb][0], acc[0][nb][2]),
                         fmaxf(acc[1][nb][0], acc[1][nb][2])) + b0;
        float v1 = fmaxf(fmaxf(acc[0][nb][1], acc[0][nb][3]),
                         fmaxf(acc[1][nb][1], acc[1][nb][3])) + b1;
        v0 = fmaxf(v0, 0.f); v1 = fmaxf(v1, 0.f);
#pragma unroll
        for (int off = 4; off <= 16; off <<= 1) {
            v0 = fmaxf(v0, __shfl_xor_sync(0xffffffffu, v0, off));
            v1 = fmaxf(v1, __shfl_xor_sync(0xffffffffu, v1, off));
        }
        if (lane < 4) {
            out[obase + col] = v0;
            out[obase + col + 1] = v1;
        }
    }
}

// =====================================================================
// mega kernel: blocks 0..15 = FPS producer; blocks 16.. = persistent
// consumers: two independent 256-thread units, each popping 4-centroid
// chunks from a global atomic queue until empty.
// =====================================================================
__global__ void __launch_bounds__(512, 1) mega_kernel(
    const float* __restrict__ xyz, const float* __restrict__ fea,
    const float* __restrict__ W1, const float* __restrict__ B1,
    const float* __restrict__ W2, const float* __restrict__ B2,
    const float* __restrict__ W3, const float* __restrict__ B3,
    float* __restrict__ out)
{
    extern __shared__ char smp[];

    if (blockIdx.x < BATCH) {
        // ================= FPS role =================
        float* sx = (float*)smp;
        float* sy = sx + NPTS;
        float* sz = sy + NPTS;
        __shared__ uint2 s_wk[2][16];

        int b = blockIdx.x, t = threadIdx.x;
        int lane = t & 31, warp = t >> 5;

        float px[16], py[16], pz[16], dist[16];
#pragma unroll
        for (int j = 0; j < 16; j++) {
            int p = t + 512 * j;
            const float* src = xyz + ((size_t)b * NPTS + p) * 3;
            float x = src[0], y = src[1], z = src[2];
            px[j] = x; py[j] = y; pz[j] = z; dist[j] = 1e10f;
            sx[p] = x; sy[p] = y; sz[p] = z;
            g_xs[b][p] = x; g_ys[b][p] = y; g_zs[b][p] = z;
            g_ss[b][p] = __fmaf_rn(z, z, __fmaf_rn(y, y, __fmul_rn(x, x)));
        }
        __threadfence();
        __syncthreads();

        int far = 0;
        for (int k = 0; k < NSAMP; k++) {
            if (t == 0) g_fps[b][k] = far;
            float cx = sx[far], cy = sy[far], cz = sz[far];

            unsigned bd = 0u;
            int bidx = 0;
#pragma unroll
            for (int j = 0; j < 16; j++) {
                float dx = __fsub_rn(px[j], cx);
                float dy = __fsub_rn(py[j], cy);
                float dz = __fsub_rn(pz[j], cz);
                float d = __fmaf_rn(dz, dz, __fmaf_rn(dy, dy, __fmul_rn(dx, dx)));
                float dm = fminf(dist[j], d);
                dist[j] = dm;
                unsigned db = __float_as_uint(dm);
                if (j == 0) { bd = db; bidx = t; }
                else if (db > bd) { bd = db; bidx = t + 512 * j; }
            }
            unsigned wmax = __reduce_max_sync(0xffffffffu, bd);
            unsigned cand = (bd == wmax) ? (unsigned)bidx : 0xffffffffu;
            unsigned widx = __reduce_min_sync(0xffffffffu, cand);
            if (lane == 0) s_wk[k & 1][warp] = make_uint2(wmax, widx);
            __syncthreads();
            uint2 v = (lane < 16) ? s_wk[k & 1][lane] : make_uint2(0u, 0xffffffffu);
            unsigned m2 = __reduce_max_sync(0xffffffffu, v.x);
            unsigned c2 = (v.x == m2) ? v.y : 0xffffffffu;
            far = (int)__reduce_min_sync(0xffffffffu, c2);

            if (t == 0 && ((k + 1) & 7) == 0) {
                __threadfence();
                *(volatile int*)&g_prog[b] = k + 1;
            }
        }
        __syncthreads();
        for (int k = t; k < NSAMP; k += 512) {
            int f = g_fps[b][k];
            size_t o = ((size_t)b * NSAMP + k) * 3;
            out[o + 0] = sx[f];
            out[o + 1] = sy[f];
            out[o + 2] = sz[f];
        }
        return;
    }

    // ================= persistent MLP consumers =================
    uint32_t sb = smem_u32(smp);
    __shared__ int s_v[2];
    int tid = threadIdx.x, lane = tid & 31;
    int unit = tid >> 8;
    int utid = tid & 255;
    int uwid = utid >> 5;
    int cent = uwid >> 1, nhalf = uwid & 1;
    int rowBase = cent * 32;

    char* aBase = smp + unit * 34816;
    char* wBase = smp + WREGION + unit * 36864;
    uint32_t aB = sb + unit * 34816;
    uint32_t wB = sb + WREGION + unit * 36864;
    int barid = 1 + unit;
#define UBAR() asm volatile("bar.sync %0, 256;" :: "r"(barid) : "memory")

    for (;;) {
        if (utid == 0) {
            int v = atomicAdd(&g_qhead, 1);
            if (v < NCHUNK) {
                int bb = v & 15, need = ((v >> 4) << 2) + 4;
                while (*(volatile int*)&g_prog[bb] < need) __nanosleep(128);
                __threadfence();
            }
            s_v[unit] = v;
        }
        UBAR();
        int v = s_v[unit];
        if (v >= NCHUNK) break;
        int b = v & 15;
        int s0 = (v >> 4) << 2;

        // phase A: warps 0-3 ball-query || warps 4-7 copy W1
        if (uwid < 4) {
            int s = s0 + uwid;
            int far = __ldcg(&g_fps[b][s]);
            float ax = g_xs[b][far], ay = g_ys[b][far], az = g_zs[b][far];
            float sa = __fmaf_rn(az, az, __fmaf_rn(ay, ay, __fmul_rn(ax, ax)));
            const float RR = 0.04f;
            int filled = 0;
            for (int base = 0; base < NPTS; base += 32) {
                int n = base + lane;
                float bx = g_xs[b][n], by = g_ys[b][n], bz = g_zs[b][n];
                float sbq = g_ss[b][n];
                float dot = __fmaf_rn(az, bz, __fmaf_rn(ay, by, __fmul_rn(ax, bx)));
                float sq = __fsub_rn(__fadd_rn(sa, sbq), __fmul_rn(2.0f, dot));
                bool inr = !(sq > RR);
                unsigned m = __ballot_sync(0xffffffffu, inr);
                int pos = filled + __popc(m & ((1u << lane) - 1u));
                if (inr && pos < NGRP) g_grp[b][s][pos] = n;
                filled += __popc(m);
                if (filled >= NGRP) break;
            }
            if (filled < NGRP) {
                __syncwarp();
                int first = g_grp[b][s][0];
                int j = filled + lane;
                if (j < NGRP) g_grp[b][s][j] = first;
            }
        } else {
            copyW(wBase,           g_W1s[0], 11264, utid - 128, 128);
            copyW(wBase + WLO_GAP, g_W1s[1], 11264, utid - 128, 128);
        }
        UBAR();

        // phase B: gather feats (128 rows)
        if (utid < 128) {
            int c = utid >> 5, g = utid & 31, s = s0 + c;
            int far = __ldcg(&g_fps[b][s]);
            int idx = g_grp[b][s][g];
            float f[80];
            f[0] = g_xs[b][idx] - g_xs[b][far];
            f[1] = g_ys[b][idx] - g_ys[b][far];
            f[2] = g_zs[b][idx] - g_zs[b][far];
            const float4* fr = (const float4*)(fea + ((size_t)b * NPTS + idx) * FDIM);
#pragma unroll
            for (int q = 0; q < 16; q++) {
                float4 vv = __ldg(fr + q);
                f[3 + 4 * q + 0] = vv.x; f[3 + 4 * q + 1] = vv.y;
                f[3 + 4 * q + 2] = vv.z; f[3 + 4 * q + 3] = vv.w;
            }
#pragma unroll
            for (int q = 67; q < 80; q++) f[q] = 0.f;
#pragma unroll
            for (int q = 0; q < 40; q++)
                storeA(aBase, utid, 2 * q, f[2 * q], f[2 * q + 1]);
        }
        UBAR();

        // L1: [128x80] @ [80x64]
        {
            float acc[2][4][4];
            warp_gemm<4, 5, 88>(aB, wB, rowBase, nhalf * 32, acc);
            UBAR();
            epi_store<4>(aBase, rowBase, nhalf * 32, B1, acc);
            copyW(wBase,           g_W2s[0], 18432, utid, 256);
            copyW(wBase + WLO_GAP, g_W2s[1], 18432, utid, 256);
            UBAR();
        }
        // L2: [128x64] @ [64x128]
        {
            float acc[2][8][4];
            warp_gemm<8, 4, 72>(aB, wB, rowBase, nhalf * 64, acc);
            UBAR();
            epi_store<8>(aBase, rowBase, nhalf * 64, B2, acc);
            copyW(wBase,           g_W3s[0], 17408, utid, 256);
            copyW(wBase + WLO_GAP, g_W3s[1], 17408, utid, 256);
            UBAR();
        }
        // L3: four 64-col chunks + maxpool
        size_t obase = (size_t)BATCH * NSAMP * 3 +
                       ((size_t)(b * NSAMP + s0 + cent)) * 256;
        {
            float acc[2][4][4];
            warp_gemm<4, 8, 136>(aB, wB, rowBase, nhalf * 32, acc);
            epi_max(nhalf * 32, B3, out, obase, acc);
            UBAR();
            copyW(wBase,           g_W3s[0] + 8704,  17408, utid, 256);
            copyW(wBase + WLO_GAP, g_W3s[1] + 8704,  17408, utid, 256);
            UBAR();
            warp_gemm<4, 8, 136>(aB, wB, rowBase, nhalf * 32, acc);
            epi_max(64 + nhalf * 32, B3, out, obase, acc);
            UBAR();
            copyW(wBase,           g_W3s[0] + 17408, 17408, utid, 256);
            copyW(wBase + WLO_GAP, g_W3s[1] + 17408, 17408, utid, 256);
            UBAR();
            warp_gemm<4, 8, 136>(aB, wB, rowBase, nhalf * 32, acc);
            epi_max(128 + nhalf * 32, B3, out, obase, acc);
            UBAR();
            copyW(wBase,           g_W3s[0] + 26112, 17408, utid, 256);
            copyW(wBase + WLO_GAP, g_W3s[1] + 26112, 17408, utid, 256);
            UBAR();
            warp_gemm<4, 8, 136>(aB, wB, rowBase, nhalf * 32, acc);
            epi_max(192 + nhalf * 32, B3, out, obase, acc);
        }
    }
#undef UBAR
}

// ---------------- launcher ----------------
extern "C" void kernel_launch(void* const* d_in, const int* in_sizes, int n_in,
                              void* d_out, int out_size) {
    (void)in_sizes; (void)n_in; (void)out_size;
    const float* xyz = (const float*)d_in[0];
    const float* fea = (const float*)d_in[1];
    const float* W1  = (const float*)d_in[2];
    const float* B1  = (const float*)d_in[3];
    const float* W2  = (const float*)d_in[4];
    const float* B2  = (const float*)d_in[5];
    const float* W3  = (const float*)d_in[6];
    const float* B3  = (const float*)d_in[7];
    float* out = (float*)d_out;

    cudaFuncSetAttribute(mega_kernel, cudaFuncAttributeMaxDynamicSharedMemorySize,
                         SMEM_TOT);

    init_kernel<<<200, 256>>>(W1, W2, W3);
    int grid = BATCH + 136;      // 16 fps + persistent consumers (~SM count)
    mega_kernel<<<grid, 512, SMEM_TOT>>>(xyz, fea, W1, B1, W2, B2, W3, B3, out);
}

// round 14
// speedup vs baseline: 3.1019x; 1.1709x over previous
#include <cuda_runtime.h>
#include <cuda_bf16.h>
#include <cstdint>
#include <cstddef>

#define BATCH 16
#define NPTS  8192
#define NSAMP 1024
#define NGRP  32
#define FDIM  64
#define NCHUNK (BATCH * NSAMP / 4)      // 4096 4-centroid work items

// ---------------- device scratch ----------------
__device__ float g_xs[BATCH][NPTS];
__device__ float g_ys[BATCH][NPTS];
__device__ float g_zs[BATCH][NPTS];
__device__ float g_ss[BATCH][NPTS];
__device__ int   g_fps[BATCH][NSAMP];
__device__ int   g_grp[BATCH][NSAMP][NGRP];
__device__ int   g_prog[BATCH];
__device__ int   g_qhead;

// B fragments pre-packed per mma lane: uint4 = {b0_hi, b1_hi, b0_lo, b1_lo}
// entry index = ((nbg*KB + kb)*32 + lane)
__device__ uint4 g_W1f[8 * 5 * 32];      // 67x64,  K padded 80
__device__ uint4 g_W2f[16 * 4 * 32];     // 64x128
__device__ uint4 g_W3f[32 * 8 * 32];     // 128x256

static __device__ __forceinline__ unsigned pkbf(float a, float b) {
    __nv_bfloat16 ha = __float2bfloat16(a), hb = __float2bfloat16(b);
    return (unsigned)__bfloat16_as_ushort(ha) |
           ((unsigned)__bfloat16_as_ushort(hb) << 16);
}
static __device__ __forceinline__ uint4 packfrag(const float* W, int K, int ldw,
                                                 int nbg, int kb, int l) {
    int n = nbg * 8 + (l >> 2);
    int k = kb * 16 + 2 * (l & 3);
    float w0 = (k     < K) ? __ldg(W + k * ldw + n)       : 0.f;
    float w1 = (k + 1 < K) ? __ldg(W + (k + 1) * ldw + n) : 0.f;
    float w8 = (k + 8 < K) ? __ldg(W + (k + 8) * ldw + n) : 0.f;
    float w9 = (k + 9 < K) ? __ldg(W + (k + 9) * ldw + n) : 0.f;
    float r0 = w0 - __bfloat162float(__float2bfloat16(w0));
    float r1 = w1 - __bfloat162float(__float2bfloat16(w1));
    float r8 = w8 - __bfloat162float(__float2bfloat16(w8));
    float r9 = w9 - __bfloat162float(__float2bfloat16(w9));
    uint4 o;
    o.x = pkbf(w0, w1); o.y = pkbf(w8, w9);
    o.z = pkbf(r0, r1); o.w = pkbf(r8, r9);
    return o;
}

__global__ void init_kernel(const float* __restrict__ W1,
                            const float* __restrict__ W2,
                            const float* __restrict__ W3) {
    int nth = gridDim.x * blockDim.x;
    int i = blockIdx.x * blockDim.x + threadIdx.x;
    if (i < BATCH) g_prog[i] = 0;
    if (i == BATCH) g_qhead = 0;
    for (int idx = i; idx < 8 * 5 * 32; idx += nth) {
        int l = idx & 31, kb = (idx >> 5) % 5, nbg = idx / 160;
        g_W1f[idx] = packfrag(W1, 67, 64, nbg, kb, l);
    }
    for (int idx = i; idx < 16 * 4 * 32; idx += nth) {
        int l = idx & 31, kb = (idx >> 5) & 3, nbg = idx >> 7;
        g_W2f[idx] = packfrag(W2, 64, 128, nbg, kb, l);
    }
    for (int idx = i; idx < 32 * 8 * 32; idx += nth) {
        int l = idx & 31, kb = (idx >> 5) & 7, nbg = idx >> 8;
        g_W3f[idx] = packfrag(W3, 128, 256, nbg, kb, l);
    }
}

// =====================================================================
// SMEM (dynamic, 139264 B):
//  consumer: unit u A hi @ u*34816, A lo @ 69632 + u*34816 ([128][136] bf16)
//  fps: sx/sy/sz[8192] f32, sidx[8192] i32, sspos[1024], cnt[512], base[512]
// =====================================================================
#define LDA       136
#define ALO_GAP   69632
#define SMEM_TOT  139264

static __device__ __forceinline__ uint32_t smem_u32(const void* p) {
    uint32_t a;
    asm("{ .reg .u64 t; cvta.to.shared.u64 t, %1; cvt.u32.u64 %0, t; }"
        : "=r"(a) : "l"(p));
    return a;
}
static __device__ __forceinline__ void ldm_x4(uint32_t* r, uint32_t addr) {
    asm volatile("ldmatrix.sync.aligned.m8n8.x4.shared.b16 {%0,%1,%2,%3}, [%4];"
                 : "=r"(r[0]), "=r"(r[1]), "=r"(r[2]), "=r"(r[3]) : "r"(addr));
}
static __device__ __forceinline__ void mma_bf16(float* c, const uint32_t* a,
                                                uint32_t b0, uint32_t b1) {
    asm volatile(
        "mma.sync.aligned.m16n8k16.row.col.f32.bf16.bf16.f32 "
        "{%0,%1,%2,%3}, {%4,%5,%6,%7}, {%8,%9}, {%0,%1,%2,%3};"
        : "+f"(c[0]), "+f"(c[1]), "+f"(c[2]), "+f"(c[3])
        : "r"(a[0]), "r"(a[1]), "r"(a[2]), "r"(a[3]), "r"(b0), "r"(b1));
}

static __device__ __forceinline__ void split2(float a, float b,
                                              unsigned& hi, unsigned& lo) {
    __nv_bfloat16 ha = __float2bfloat16(a), hb = __float2bfloat16(b);
    float ra = a - __bfloat162float(ha), rb = b - __bfloat162float(hb);
    __nv_bfloat16 la = __float2bfloat16(ra), lb = __float2bfloat16(rb);
    hi = (unsigned)__bfloat16_as_ushort(ha) | ((unsigned)__bfloat16_as_ushort(hb) << 16);
    lo = (unsigned)__bfloat16_as_ushort(la) | ((unsigned)__bfloat16_as_ushort(lb) << 16);
}
static __device__ __forceinline__ void storeA(char* aBase, int row, int col,
                                              float a, float b) {
    unsigned h, l;
    split2(a, b, h, l);
    int off = (row * LDA + col) * 2;
    *(unsigned*)(aBase + off) = h;
    *(unsigned*)(aBase + ALO_GAP + off) = l;
}

// warp GEMM with B fragments loaded straight from packed global arrays.
// Per-accumulator mma order identical to the smem version (bit-exact).
template <int NBLK, int KSTEPS>
static __device__ __forceinline__ void warp_gemm_ldg(
    uint32_t aB, const uint4* __restrict__ Wf, int nbgBase, int KB,
    int rowBase, float (&acc)[2][NBLK][4])
{
    int lane = threadIdx.x & 31;
#pragma unroll
    for (int m = 0; m < 2; m++)
#pragma unroll
        for (int nb = 0; nb < NBLK; nb++)
#pragma unroll
            for (int i = 0; i < 4; i++) acc[m][nb][i] = 0.f;

    int arow = lane & 15;
    int acolo = (lane >> 4) << 3;

#pragma unroll
    for (int k = 0; k < KSTEPS; k++) {
        int k0 = k << 4;
        uint32_t ah[2][4], al[2][4];
#pragma unroll
        for (int m = 0; m < 2; m++) {
            uint32_t ao = (uint32_t)(((rowBase + m * 16 + arow) * LDA + k0 + acolo) * 2);
            ldm_x4(ah[m], aB + ao);
            ldm_x4(al[m], aB + ALO_GAP + ao);
        }
#pragma unroll
        for (int g = 0; g < NBLK; g += 4) {
            uint4 f[4];
#pragma unroll
            for (int q = 0; q < 4 && g + q < NBLK; q++)
                f[q] = __ldg(&Wf[((nbgBase + g + q) * KB + k) * 32 + lane]);
#pragma unroll
            for (int q = 0; q < 4 && g + q < NBLK; q++) {
#pragma unroll
                for (int m = 0; m < 2; m++) {
                    mma_bf16(acc[m][g + q], ah[m], f[q].x, f[q].y);
                    mma_bf16(acc[m][g + q], ah[m], f[q].z, f[q].w);
                    mma_bf16(acc[m][g + q], al[m], f[q].x, f[q].y);
                }
            }
        }
    }
}

template <int NBLK>
static __device__ __forceinline__ void epi_store(char* aBase, int rowBase, int colBase,
                                                 const float* __restrict__ bias,
                                                 float (&acc)[2][NBLK][4]) {
    int lane = threadIdx.x & 31;
    int cq = (lane & 3) * 2;
    int rq = lane >> 2;
#pragma unroll
    for (int nb = 0; nb < NBLK; nb++) {
        int col = colBase + nb * 8 + cq;
        float b0 = __ldg(bias + col), b1 = __ldg(bias + col + 1);
#pragma unroll
        for (int m = 0; m < 2; m++) {
            int row = rowBase + m * 16 + rq;
            float v0 = fmaxf(acc[m][nb][0] + b0, 0.f);
            float v1 = fmaxf(acc[m][nb][1] + b1, 0.f);
            float v2 = fmaxf(acc[m][nb][2] + b0, 0.f);
            float v3 = fmaxf(acc[m][nb][3] + b1, 0.f);
            storeA(aBase, row, col, v0, v1);
            storeA(aBase, row + 8, col, v2, v3);
        }
    }
}

static __device__ __forceinline__ void epi_max(int gColBase, const float* __restrict__ B3,
                                               float* __restrict__ out, size_t obase,
                                               float (&acc)[2][4][4]) {
    int lane = threadIdx.x & 31;
    int cq = (lane & 3) * 2;
#pragma unroll
    for (int nb = 0; nb < 4; nb++) {
        int col = gColBase + nb * 8 + cq;
        float b0 = __ldg(B3 + col), b1 = __ldg(B3 + col + 1);
        float v0 = fmaxf(fmaxf(acc[0][nb][0], acc[0][nb][2]),
                         fmaxf(acc[1][nb][0], acc[1][nb][2])) + b0;
        float v1 = fmaxf(fmaxf(acc[0][nb][1], acc[0][nb][3]),
                         fmaxf(acc[1][nb][1], acc[1][nb][3])) + b1;
        v0 = fmaxf(v0, 0.f); v1 = fmaxf(v1, 0.f);
#pragma unroll
        for (int off = 4; off <= 16; off <<= 1) {
            v0 = fmaxf(v0, __shfl_xor_sync(0xffffffffu, v0, off));
            v1 = fmaxf(v1, __shfl_xor_sync(0xffffffffu, v1, off));
        }
        if (lane < 4) {
            out[obase + col] = v0;
            out[obase + col + 1] = v1;
        }
    }
}

static __device__ __forceinline__ unsigned spread3(unsigned v) {
    return (v & 1u) | ((v & 2u) << 2) | ((v & 4u) << 4);
}

// =====================================================================
// mega kernel: blocks 0..15 run Morton-pruned FPS, then CONVERT to
// consumers; blocks 16.. are persistent consumers from the start.
// =====================================================================
__global__ void __launch_bounds__(512, 1) mega_kernel(
    const float* __restrict__ xyz, const float* __restrict__ fea,
    const float* __restrict__ W1, const float* __restrict__ B1,
    const float* __restrict__ W2, const float* __restrict__ B2,
    const float* __restrict__ W3, const float* __restrict__ B3,
    float* __restrict__ out)
{
    extern __shared__ char smp[];
    __shared__ uint2 s_wk[2][16];
    __shared__ int s_v[2];
    __shared__ int s_far0;

    if (blockIdx.x < BATCH) {
        // ================= FPS role (Morton-sorted, box-pruned) =========
        float* sx = (float*)smp;
        float* sy = sx + NPTS;
        float* sz = sy + NPTS;
        int* sidx = (int*)(sz + NPTS);
        int* sspos = sidx + NPTS;
        int* scnt = sspos + NSAMP;
        int* sbase = scnt + 512;

        int b = blockIdx.x, t = threadIdx.x;
        int lane = t & 31, warp = t >> 5;

        float px[16], py[16], pz[16], dist[16];
        int cid[16];
        // load, publish unsorted arrays, compute Morton cell ids
        if (t < 512) scnt[t] = 0;
        __syncthreads();
#pragma unroll
        for (int j = 0; j < 16; j++) {
            int p = t + 512 * j;
            const float* src = xyz + ((size_t)b * NPTS + p) * 3;
            float x = src[0], y = src[1], z = src[2];
            px[j] = x; py[j] = y; pz[j] = z;
            g_xs[b][p] = x; g_ys[b][p] = y; g_zs[b][p] = z;
            g_ss[b][p] = __fmaf_rn(z, z, __fmaf_rn(y, y, __fmul_rn(x, x)));
            unsigned ix = min(7, (int)(x * 8.f));
            unsigned iy = min(7, (int)(y * 8.f));
            unsigned iz = min(7, (int)(z * 8.f));
            cid[j] = (int)(spread3(ix) | (spread3(iy) << 1) | (spread3(iz) << 2));
            atomicAdd(&scnt[cid[j]], 1);
        }
        __threadfence();      // publish g_* before any prog post
        __syncthreads();
        // exclusive scan over 512 cells (warp 0)
        if (warp == 0) {
            int c0 = lane * 16, s = 0;
#pragma unroll
            for (int i = 0; i < 16; i++) s += scnt[c0 + i];
            int off = s;
#pragma unroll
            for (int d = 1; d < 32; d <<= 1) {
                int n = __shfl_up_sync(0xffffffffu, off, d);
                if (lane >= d) off += n;
            }
            off -= s;
            int run = off;
#pragma unroll
            for (int i = 0; i < 16; i++) {
                int c = scnt[c0 + i];
                sbase[c0 + i] = run;
                run += c;
            }
        }
        __syncthreads();
        // scatter (sorted arrays + orig index)
#pragma unroll
        for (int j = 0; j < 16; j++) {
            int pos = atomicAdd(&sbase[cid[j]], 1);
            sx[pos] = px[j]; sy[pos] = py[j]; sz[pos] = pz[j];
            sidx[pos] = t + 512 * j;
            if (t == 0 && j == 0) s_far0 = pos;   // orig point 0
        }
        __syncthreads();
        // reload sorted points + bounding box
        float lox = 1e9f, hix = -1e9f, loy = 1e9f, hiy = -1e9f,
              loz = 1e9f, hiz = -1e9f;
#pragma unroll
        for (int j = 0; j < 16; j++) {
            int p = 16 * t + j;
            float x = sx[p], y = sy[p], z = sz[p];
            px[j] = x; py[j] = y; pz[j] = z; dist[j] = 1e10f;
            lox = fminf(lox, x); hix = fmaxf(hix, x);
            loy = fminf(loy, y); hiy = fmaxf(hiy, y);
            loz = fminf(loz, z); hiz = fmaxf(hiz, z);
        }
        float tmax = 1e10f;
        int far_orig = 0, far_spos = s_far0;

        for (int k = 0; k < NSAMP; k++) {
            if (t == 0) { g_fps[b][k] = far_orig; sspos[k] = far_spos; }
            float cx = sx[far_spos], cy = sy[far_spos], cz = sz[far_spos];

            float dxl = fmaxf(fmaxf(__fsub_rn(lox, cx), __fsub_rn(cx, hix)), 0.f);
            float dyl = fmaxf(fmaxf(__fsub_rn(loy, cy), __fsub_rn(cy, hiy)), 0.f);
            float dzl = fmaxf(fmaxf(__fsub_rn(loz, cz), __fsub_rn(cz, hiz)), 0.f);
            float bound = dxl * dxl + dyl * dyl + dzl * dzl;

            if (!(bound * 0.999f > tmax)) {
                float nm = 0.f;
#pragma unroll
                for (int j = 0; j < 16; j++) {
                    float dx = __fsub_rn(px[j], cx);
                    float dy = __fsub_rn(py[j], cy);
                    float dz = __fsub_rn(pz[j], cz);
                    float d = __fmaf_rn(dz, dz, __fmaf_rn(dy, dy, __fmul_rn(dx, dx)));
                    float dm = fminf(dist[j], d);
                    dist[j] = dm;
                    nm = fmaxf(nm, dm);
                }
                tmax = nm;
            }
            unsigned tb = __float_as_uint(tmax);
            unsigned wmax = __reduce_max_sync(0xffffffffu, tb);
            unsigned cand = 0xffffffffu;
            if (tb == wmax) {
#pragma unroll
                for (int j = 0; j < 16; j++)
                    if (__float_as_uint(dist[j]) == wmax) {
                        int sp = 16 * t + j;
                        unsigned key = ((unsigned)sidx[sp] << 13) | (unsigned)sp;
                        cand = min(cand, key);
                    }
            }
            unsigned widx = __reduce_min_sync(0xffffffffu, cand);
            if (lane == 0) s_wk[k & 1][warp] = make_uint2(wmax, widx);
            __syncthreads();
            uint2 v = (lane < 16) ? s_wk[k & 1][lane] : make_uint2(0u, 0xffffffffu);
            unsigned m2 = __reduce_max_sync(0xffffffffu, v.x);
            unsigned c2 = (v.x == m2) ? v.y : 0xffffffffu;
            c2 = __reduce_min_sync(0xffffffffu, c2);
            far_orig = (int)(c2 >> 13);
            far_spos = (int)(c2 & 8191u);

            if (t == 0 && ((k + 1) & 7) == 0) {
                __threadfence();
                *(volatile int*)&g_prog[b] = k + 1;
            }
        }
        __syncthreads();
        for (int k = t; k < NSAMP; k += 512) {
            int sp = sspos[k];
            size_t o = ((size_t)b * NSAMP + k) * 3;
            out[o + 0] = sx[sp];
            out[o + 1] = sy[sp];
            out[o + 2] = sz[sp];
        }
        __syncthreads();
        // fall through: convert to consumer
    }

    // ================= persistent MLP consumers =================
    uint32_t sb = smem_u32(smp);
    int tid = threadIdx.x, lane = tid & 31;
    int unit = tid >> 8;
    int utid = tid & 255;
    int uwid = utid >> 5;
    int cent = uwid >> 1, nhalf = uwid & 1;
    int rowBase = cent * 32;

    char* aBase = smp + unit * 34816;
    uint32_t aB = sb + unit * 34816;
    int barid = 1 + unit;
#define UBAR() asm volatile("bar.sync %0, 256;" :: "r"(barid) : "memory")

    for (;;) {
        if (utid == 0) {
            int v = atomicAdd(&g_qhead, 1);
            if (v < NCHUNK) {
                int bb = v & 15, need = ((v >> 4) << 2) + 4;
                while (*(volatile int*)&g_prog[bb] < need) __nanosleep(128);
                __threadfence();
            }
            s_v[unit] = v;
        }
        UBAR();
        int v = s_v[unit];
        if (v >= NCHUNK) break;
        int b = v & 15;
        int s0 = (v >> 4) << 2;

        // phase A: warps 0-3 ball-query one centroid each
        if (uwid < 4) {
            int s = s0 + uwid;
            int far = __ldcg(&g_fps[b][s]);
            float ax = g_xs[b][far], ay = g_ys[b][far], az = g_zs[b][far];
            float sa = __fmaf_rn(az, az, __fmaf_rn(ay, ay, __fmul_rn(ax, ax)));
            const float RR = 0.04f;
            int filled = 0;
            for (int base = 0; base < NPTS; base += 32) {
                int n = base + lane;
                float bx = g_xs[b][n], by = g_ys[b][n], bz = g_zs[b][n];
                float sbq = g_ss[b][n];
                float dot = __fmaf_rn(az, bz, __fmaf_rn(ay, by, __fmul_rn(ax, bx)));
                float sq = __fsub_rn(__fadd_rn(sa, sbq), __fmul_rn(2.0f, dot));
                bool inr = !(sq > RR);
                unsigned m = __ballot_sync(0xffffffffu, inr);
                int pos = filled + __popc(m & ((1u << lane) - 1u));
                if (inr && pos < NGRP) g_grp[b][s][pos] = n;
                filled += __popc(m);
                if (filled >= NGRP) break;
            }
            if (filled < NGRP) {
                __syncwarp();
                int first = g_grp[b][s][0];
                int j = filled + lane;
                if (j < NGRP) g_grp[b][s][j] = first;
            }
        }
        UBAR();

        // phase B: gather feats (128 rows)
        if (utid < 128) {
            int c = utid >> 5, g = utid & 31, s = s0 + c;
            int far = __ldcg(&g_fps[b][s]);
            int idx = g_grp[b][s][g];
            float f[80];
            f[0] = g_xs[b][idx] - g_xs[b][far];
            f[1] = g_ys[b][idx] - g_ys[b][far];
            f[2] = g_zs[b][idx] - g_zs[b][far];
            const float4* fr = (const float4*)(fea + ((size_t)b * NPTS + idx) * FDIM);
#pragma unroll
            for (int q = 0; q < 16; q++) {
                float4 vv = __ldg(fr + q);
                f[3 + 4 * q + 0] = vv.x; f[3 + 4 * q + 1] = vv.y;
                f[3 + 4 * q + 2] = vv.z; f[3 + 4 * q + 3] = vv.w;
            }
#pragma unroll
            for (int q = 67; q < 80; q++) f[q] = 0.f;
#pragma unroll
            for (int q = 0; q < 40; q++)
                storeA(aBase, utid, 2 * q, f[2 * q], f[2 * q + 1]);
        }
        UBAR();

        // L1: [128x80] @ [80x64]
        {
            float acc[2][4][4];
            warp_gemm_ldg<4, 5>(aB, g_W1f, nhalf * 4, 5, rowBase, acc);
            UBAR();
            epi_store<4>(aBase, rowBase, nhalf * 32, B1, acc);
            UBAR();
        }
        // L2: [128x64] @ [64x128]
        {
            float acc[2][8][4];
            warp_gemm_ldg<8, 4>(aB, g_W2f, nhalf * 8, 4, rowBase, acc);
            UBAR();
            epi_store<8>(aBase, rowBase, nhalf * 64, B2, acc);
            UBAR();
        }
        // L3: [128x128] @ [128x256] as 4 barrier-free sub-GEMMs + maxpool
        size_t obase = (size_t)BATCH * NSAMP * 3 +
                       ((size_t)(b * NSAMP + s0 + cent)) * 256;
        {
            float acc[2][4][4];
#pragma unroll
            for (int ci = 0; ci < 4; ci++) {
                warp_gemm_ldg<4, 8>(aB, g_W3f, ci * 8 + nhalf * 4, 8, rowBase, acc);
                epi_max(ci * 64 + nhalf * 32, B3, out, obase, acc);
            }
        }
    }
#undef UBAR
}

// ---------------- launcher ----------------
extern "C" void kernel_launch(void* const* d_in, const int* in_sizes, int n_in,
                              void* d_out, int out_size) {
    (void)in_sizes; (void)n_in; (void)out_size;
    const float* xyz = (const float*)d_in[0];
    const float* fea = (const float*)d_in[1];
    const float* W1  = (const float*)d_in[2];
    const float* B1  = (const float*)d_in[3];
    const float* W2  = (const float*)d_in[4];
    const float* B2  = (const float*)d_in[5];
    const float* W3  = (const float*)d_in[6];
    const float* B3  = (const float*)d_in[7];
    float* out = (float*)d_out;

    cudaFuncSetAttribute(mega_kernel, cudaFuncAttributeMaxDynamicSharedMemorySize,
                         SMEM_TOT);

    init_kernel<<<200, 256>>>(W1, W2, W3);
    int grid = BATCH + 136;
    mega_kernel<<<grid, 512, SMEM_TOT>>>(xyz, fea, W1, B1, W2, B2, W3, B3, out);
}

// round 15
// speedup vs baseline: 3.1596x; 1.0186x over previous
#include <cuda_runtime.h>
#include <cuda_bf16.h>
#include <cstdint>
#include <cstddef>

#define BATCH 16
#define NPTS  8192
#define NSAMP 1024
#define NGRP  32
#define FDIM  64
#define NITEM (BATCH * NSAMP)            // 16384 single-centroid work items

// ---------------- device scratch ----------------
__device__ float4 g_p4[BATCH][NPTS];     // x,y,z,sumsq
__device__ int    g_fps[BATCH][NSAMP];
__device__ int    g_grp[BATCH][NSAMP][NGRP];
__device__ int    g_prog[BATCH];
__device__ int    g_qhead;

// B fragments pre-packed per mma lane: uint4 = {b0_hi, b1_hi, b0_lo, b1_lo}
__device__ uint4 g_W1f[8 * 5 * 32];
__device__ uint4 g_W2f[16 * 4 * 32];
__device__ uint4 g_W3f[32 * 8 * 32];

static __device__ __forceinline__ unsigned pkbf(float a, float b) {
    __nv_bfloat16 ha = __float2bfloat16(a), hb = __float2bfloat16(b);
    return (unsigned)__bfloat16_as_ushort(ha) |
           ((unsigned)__bfloat16_as_ushort(hb) << 16);
}
static __device__ __forceinline__ uint4 packfrag(const float* W, int K, int ldw,
                                                 int nbg, int kb, int l) {
    int n = nbg * 8 + (l >> 2);
    int k = kb * 16 + 2 * (l & 3);
    float w0 = (k     < K) ? __ldg(W + k * ldw + n)       : 0.f;
    float w1 = (k + 1 < K) ? __ldg(W + (k + 1) * ldw + n) : 0.f;
    float w8 = (k + 8 < K) ? __ldg(W + (k + 8) * ldw + n) : 0.f;
    float w9 = (k + 9 < K) ? __ldg(W + (k + 9) * ldw + n) : 0.f;
    float r0 = w0 - __bfloat162float(__float2bfloat16(w0));
    float r1 = w1 - __bfloat162float(__float2bfloat16(w1));
    float r8 = w8 - __bfloat162float(__float2bfloat16(w8));
    float r9 = w9 - __bfloat162float(__float2bfloat16(w9));
    uint4 o;
    o.x = pkbf(w0, w1); o.y = pkbf(w8, w9);
    o.z = pkbf(r0, r1); o.w = pkbf(r8, r9);
    return o;
}

__global__ void init_kernel(const float* __restrict__ W1,
                            const float* __restrict__ W2,
                            const float* __restrict__ W3) {
    int nth = gridDim.x * blockDim.x;
    int i = blockIdx.x * blockDim.x + threadIdx.x;
    if (i < BATCH) g_prog[i] = 0;
    if (i == BATCH) g_qhead = 0;
    for (int idx = i; idx < 8 * 5 * 32; idx += nth) {
        int l = idx & 31, kb = (idx >> 5) % 5, nbg = idx / 160;
        g_W1f[idx] = packfrag(W1, 67, 64, nbg, kb, l);
    }
    for (int idx = i; idx < 16 * 4 * 32; idx += nth) {
        int l = idx & 31, kb = (idx >> 5) & 3, nbg = idx >> 7;
        g_W2f[idx] = packfrag(W2, 64, 128, nbg, kb, l);
    }
    for (int idx = i; idx < 32 * 8 * 32; idx += nth) {
        int l = idx & 31, kb = (idx >> 5) & 7, nbg = idx >> 8;
        g_W3f[idx] = packfrag(W3, 128, 256, nbg, kb, l);
    }
}

// =====================================================================
// SMEM (dynamic, 139264 B):
//  consumer: pair p (0..7): A hi @ p*8704 ([32][136] bf16), A lo @ +69632
//  fps: sx/sy/sz[8192] f32, sidx[8192] i32, sspos[1024], cnt[512], base[512]
// =====================================================================
#define LDA       136
#define ALO_GAP   69632
#define PAIR_A    8704
#define SMEM_TOT  139264

static __device__ __forceinline__ uint32_t smem_u32(const void* p) {
    uint32_t a;
    asm("{ .reg .u64 t; cvta.to.shared.u64 t, %1; cvt.u32.u64 %0, t; }"
        : "=r"(a) : "l"(p));
    return a;
}
static __device__ __forceinline__ void ldm_x4(uint32_t* r, uint32_t addr) {
    asm volatile("ldmatrix.sync.aligned.m8n8.x4.shared.b16 {%0,%1,%2,%3}, [%4];"
                 : "=r"(r[0]), "=r"(r[1]), "=r"(r[2]), "=r"(r[3]) : "r"(addr));
}
static __device__ __forceinline__ void mma_bf16(float* c, const uint32_t* a,
                                                uint32_t b0, uint32_t b1) {
    asm volatile(
        "mma.sync.aligned.m16n8k16.row.col.f32.bf16.bf16.f32 "
        "{%0,%1,%2,%3}, {%4,%5,%6,%7}, {%8,%9}, {%0,%1,%2,%3};"
        : "+f"(c[0]), "+f"(c[1]), "+f"(c[2]), "+f"(c[3])
        : "r"(a[0]), "r"(a[1]), "r"(a[2]), "r"(a[3]), "r"(b0), "r"(b1));
}

static __device__ __forceinline__ void split2(float a, float b,
                                              unsigned& hi, unsigned& lo) {
    __nv_bfloat16 ha = __float2bfloat16(a), hb = __float2bfloat16(b);
    float ra = a - __bfloat162float(ha), rb = b - __bfloat162float(hb);
    __nv_bfloat16 la = __float2bfloat16(ra), lb = __float2bfloat16(rb);
    hi = (unsigned)__bfloat16_as_ushort(ha) | ((unsigned)__bfloat16_as_ushort(hb) << 16);
    lo = (unsigned)__bfloat16_as_ushort(la) | ((unsigned)__bfloat16_as_ushort(lb) << 16);
}
static __device__ __forceinline__ void storeA(char* aBase, int row, int col,
                                              float a, float b) {
    unsigned h, l;
    split2(a, b, h, l);
    int off = (row * LDA + col) * 2;
    *(unsigned*)(aBase + off) = h;
    *(unsigned*)(aBase + ALO_GAP + off) = l;
}

// warp GEMM over the pair's 32 rows; B fragments from packed global arrays.
template <int NBLK, int KSTEPS>
static __device__ __forceinline__ void warp_gemm_ldg(
    uint32_t aB, const uint4* __restrict__ Wf, int nbgBase, int KB,
    float (&acc)[2][NBLK][4])
{
    int lane = threadIdx.x & 31;
#pragma unroll
    for (int m = 0; m < 2; m++)
#pragma unroll
        for (int nb = 0; nb < NBLK; nb++)
#pragma unroll
            for (int i = 0; i < 4; i++) acc[m][nb][i] = 0.f;

    int arow = lane & 15;
    int acolo = (lane >> 4) << 3;

#pragma unroll
    for (int k = 0; k < KSTEPS; k++) {
        int k0 = k << 4;
        uint32_t ah[2][4], al[2][4];
#pragma unroll
        for (int m = 0; m < 2; m++) {
            uint32_t ao = (uint32_t)(((m * 16 + arow) * LDA + k0 + acolo) * 2);
            ldm_x4(ah[m], aB + ao);
            ldm_x4(al[m], aB + ALO_GAP + ao);
        }
#pragma unroll
        for (int g = 0; g < NBLK; g += 4) {
            uint4 f[4];
#pragma unroll
            for (int q = 0; q < 4 && g + q < NBLK; q++)
                f[q] = __ldg(&Wf[((nbgBase + g + q) * KB + k) * 32 + lane]);
#pragma unroll
            for (int q = 0; q < 4 && g + q < NBLK; q++) {
#pragma unroll
                for (int m = 0; m < 2; m++) {
                    mma_bf16(acc[m][g + q], ah[m], f[q].x, f[q].y);
                    mma_bf16(acc[m][g + q], ah[m], f[q].z, f[q].w);
                    mma_bf16(acc[m][g + q], al[m], f[q].x, f[q].y);
                }
            }
        }
    }
}

template <int NBLK>
static __device__ __forceinline__ void epi_store(char* aBase, int colBase,
                                                 const float* __restrict__ bias,
                                                 float (&acc)[2][NBLK][4]) {
    int lane = threadIdx.x & 31;
    int cq = (lane & 3) * 2;
    int rq = lane >> 2;
#pragma unroll
    for (int nb = 0; nb < NBLK; nb++) {
        int col = colBase + nb * 8 + cq;
        float b0 = __ldg(bias + col), b1 = __ldg(bias + col + 1);
#pragma unroll
        for (int m = 0; m < 2; m++) {
            int row = m * 16 + rq;
            float v0 = fmaxf(acc[m][nb][0] + b0, 0.f);
            float v1 = fmaxf(acc[m][nb][1] + b1, 0.f);
            float v2 = fmaxf(acc[m][nb][2] + b0, 0.f);
            float v3 = fmaxf(acc[m][nb][3] + b1, 0.f);
            storeA(aBase, row, col, v0, v1);
            storeA(aBase, row + 8, col, v2, v3);
        }
    }
}

static __device__ __forceinline__ void epi_max(int gColBase, const float* __restrict__ B3,
                                               float* __restrict__ out, size_t obase,
                                               float (&acc)[2][4][4]) {
    int lane = threadIdx.x & 31;
    int cq = (lane & 3) * 2;
#pragma unroll
    for (int nb = 0; nb < 4; nb++) {
        int col = gColBase + nb * 8 + cq;
        float b0 = __ldg(B3 + col), b1 = __ldg(B3 + col + 1);
        float v0 = fmaxf(fmaxf(acc[0][nb][0], acc[0][nb][2]),
                         fmaxf(acc[1][nb][0], acc[1][nb][2])) + b0;
        float v1 = fmaxf(fmaxf(acc[0][nb][1], acc[0][nb][3]),
                         fmaxf(acc[1][nb][1], acc[1][nb][3])) + b1;
        v0 = fmaxf(v0, 0.f); v1 = fmaxf(v1, 0.f);
#pragma unroll
        for (int off = 4; off <= 16; off <<= 1) {
            v0 = fmaxf(v0, __shfl_xor_sync(0xffffffffu, v0, off));
            v1 = fmaxf(v1, __shfl_xor_sync(0xffffffffu, v1, off));
        }
        if (lane < 4) {
            out[obase + col] = v0;
            out[obase + col + 1] = v1;
        }
    }
}

static __device__ __forceinline__ unsigned spread3(unsigned v) {
    return (v & 1u) | ((v & 2u) << 2) | ((v & 4u) << 4);
}

// =====================================================================
// mega kernel: blocks 0..15 run Morton-pruned FPS then convert; all
// consumer blocks = 8 independent warp-PAIR pipelines, 1 centroid/item.
// =====================================================================
__global__ void __launch_bounds__(512, 1) mega_kernel(
    const float* __restrict__ xyz, const float* __restrict__ fea,
    const float* __restrict__ W1, const float* __restrict__ B1,
    const float* __restrict__ W2, const float* __restrict__ B2,
    const float* __restrict__ W3, const float* __restrict__ B3,
    float* __restrict__ out)
{
    extern __shared__ char smp[];
    __shared__ uint2 s_wk[2][16];
    __shared__ int s_item[8];
    __shared__ int s_far0;

    if (blockIdx.x < BATCH) {
        // ================= FPS role (Morton-sorted, box-pruned) =========
        float* sx = (float*)smp;
        float* sy = sx + NPTS;
        float* sz = sy + NPTS;
        int* sidx = (int*)(sz + NPTS);
        int* sspos = sidx + NPTS;
        int* scnt = sspos + NSAMP;
        int* sbase = scnt + 512;

        int b = blockIdx.x, t = threadIdx.x;
        int lane = t & 31, warp = t >> 5;

        float px[16], py[16], pz[16], dist[16];
        int cid[16];
        if (t < 512) scnt[t] = 0;
        __syncthreads();
#pragma unroll
        for (int j = 0; j < 16; j++) {
            int p = t + 512 * j;
            const float* src = xyz + ((size_t)b * NPTS + p) * 3;
            float x = src[0], y = src[1], z = src[2];
            px[j] = x; py[j] = y; pz[j] = z;
            g_p4[b][p] = make_float4(x, y, z,
                __fmaf_rn(z, z, __fmaf_rn(y, y, __fmul_rn(x, x))));
            unsigned ix = min(7, (int)(x * 8.f));
            unsigned iy = min(7, (int)(y * 8.f));
            unsigned iz = min(7, (int)(z * 8.f));
            cid[j] = (int)(spread3(ix) | (spread3(iy) << 1) | (spread3(iz) << 2));
            atomicAdd(&scnt[cid[j]], 1);
        }
        __threadfence();
        __syncthreads();
        if (warp == 0) {
            int c0 = lane * 16, s = 0;
#pragma unroll
            for (int i = 0; i < 16; i++) s += scnt[c0 + i];
            int off = s;
#pragma unroll
            for (int d = 1; d < 32; d <<= 1) {
                int n = __shfl_up_sync(0xffffffffu, off, d);
                if (lane >= d) off += n;
            }
            off -= s;
            int run = off;
#pragma unroll
            for (int i = 0; i < 16; i++) {
                int c = scnt[c0 + i];
                sbase[c0 + i] = run;
                run += c;
            }
        }
        __syncthreads();
#pragma unroll
        for (int j = 0; j < 16; j++) {
            int pos = atomicAdd(&sbase[cid[j]], 1);
            sx[pos] = px[j]; sy[pos] = py[j]; sz[pos] = pz[j];
            sidx[pos] = t + 512 * j;
            if (t == 0 && j == 0) s_far0 = pos;
        }
        __syncthreads();
        float lox = 1e9f, hix = -1e9f, loy = 1e9f, hiy = -1e9f,
              loz = 1e9f, hiz = -1e9f;
#pragma unroll
        for (int j = 0; j < 16; j++) {
            int p = 16 * t + j;
            float x = sx[p], y = sy[p], z = sz[p];
            px[j] = x; py[j] = y; pz[j] = z; dist[j] = 1e10f;
            lox = fminf(lox, x); hix = fmaxf(hix, x);
            loy = fminf(loy, y); hiy = fmaxf(hiy, y);
            loz = fminf(loz, z); hiz = fmaxf(hiz, z);
        }
        float tmax = 1e10f;
        int far_orig = 0, far_spos = s_far0;

        for (int k = 0; k < NSAMP; k++) {
            if (t == 0) { g_fps[b][k] = far_orig; sspos[k] = far_spos; }
            float cx = sx[far_spos], cy = sy[far_spos], cz = sz[far_spos];

            float dxl = fmaxf(fmaxf(__fsub_rn(lox, cx), __fsub_rn(cx, hix)), 0.f);
            float dyl = fmaxf(fmaxf(__fsub_rn(loy, cy), __fsub_rn(cy, hiy)), 0.f);
            float dzl = fmaxf(fmaxf(__fsub_rn(loz, cz), __fsub_rn(cz, hiz)), 0.f);
            float bound = dxl * dxl + dyl * dyl + dzl * dzl;

            if (!(bound * 0.999f > tmax)) {
                float nm = 0.f;
#pragma unroll
                for (int j = 0; j < 16; j++) {
                    float dx = __fsub_rn(px[j], cx);
                    float dy = __fsub_rn(py[j], cy);
                    float dz = __fsub_rn(pz[j], cz);
                    float d = __fmaf_rn(dz, dz, __fmaf_rn(dy, dy, __fmul_rn(dx, dx)));
                    float dm = fminf(dist[j], d);
                    dist[j] = dm;
                    nm = fmaxf(nm, dm);
                }
                tmax = nm;
            }
            unsigned tb = __float_as_uint(tmax);
            unsigned wmax = __reduce_max_sync(0xffffffffu, tb);
            unsigned cand = 0xffffffffu;
            if (tb == wmax) {
#pragma unroll
                for (int j = 0; j < 16; j++)
                    if (__float_as_uint(dist[j]) == wmax) {
                        int sp = 16 * t + j;
                        unsigned key = ((unsigned)sidx[sp] << 13) | (unsigned)sp;
                        cand = min(cand, key);
                    }
            }
            unsigned widx = __reduce_min_sync(0xffffffffu, cand);
            if (lane == 0) s_wk[k & 1][warp] = make_uint2(wmax, widx);
            __syncthreads();
            uint2 v = (lane < 16) ? s_wk[k & 1][lane] : make_uint2(0u, 0xffffffffu);
            unsigned m2 = __reduce_max_sync(0xffffffffu, v.x);
            unsigned c2 = (v.x == m2) ? v.y : 0xffffffffu;
            c2 = __reduce_min_sync(0xffffffffu, c2);
            far_orig = (int)(c2 >> 13);
            far_spos = (int)(c2 & 8191u);

            if (t == 0 && ((k + 1) & 7) == 0) {
                __threadfence();
                *(volatile int*)&g_prog[b] = k + 1;
            }
        }
        __syncthreads();
        for (int k = t; k < NSAMP; k += 512) {
            int sp = sspos[k];
            size_t o = ((size_t)b * NSAMP + k) * 3;
            out[o + 0] = sx[sp];
            out[o + 1] = sy[sp];
            out[o + 2] = sz[sp];
        }
        __syncthreads();
        // fall through: convert to consumer
    }

    // ========== persistent consumers: 8 independent warp-pair pipelines ====
    uint32_t sb = smem_u32(smp);
    int tid = threadIdx.x, lane = tid & 31;
    int wid = tid >> 5;
    int pair = wid >> 1;
    int nhalf = wid & 1;
    int ptid = tid & 63;                 // id within pair

    char* aBase = smp + pair * PAIR_A;
    uint32_t aB = sb + pair * PAIR_A;
    int barid = 1 + pair;
#define PBAR() asm volatile("bar.sync %0, 64;" :: "r"(barid) : "memory")

    for (;;) {
        if (ptid == 0) {
            int v = atomicAdd(&g_qhead, 1);
            if (v < NITEM) {
                int bb = v & 15, need = (v >> 4) + 1;
                while (*(volatile int*)&g_prog[bb] < need) __nanosleep(128);
                __threadfence();
            }
            s_item[pair] = v;
        }
        PBAR();
        int v = s_item[pair];
        if (v >= NITEM) break;
        int b = v & 15;
        int s = v >> 4;
        int far = __ldcg(&g_fps[b][s]);

        // ballq by even warp of the pair
        if (nhalf == 0) {
            float4 c4 = __ldg(&g_p4[b][far]);
            float ax = c4.x, ay = c4.y, az = c4.z, sa = c4.w;
            const float RR = 0.04f;
            int filled = 0;
            for (int base = 0; base < NPTS; base += 32) {
                int n = base + lane;
                float4 p = __ldg(&g_p4[b][n]);
                float dot = __fmaf_rn(az, p.z, __fmaf_rn(ay, p.y, __fmul_rn(ax, p.x)));
                float sq = __fsub_rn(__fadd_rn(sa, p.w), __fmul_rn(2.0f, dot));
                bool inr = !(sq > RR);
                unsigned m = __ballot_sync(0xffffffffu, inr);
                int pos = filled + __popc(m & ((1u << lane) - 1u));
                if (inr && pos < NGRP) g_grp[b][s][pos] = n;
                filled += __popc(m);
                if (filled >= NGRP) break;
            }
            if (filled < NGRP) {
                __syncwarp();
                int first = g_grp[b][s][0];
                int j = filled + lane;
                if (j < NGRP) g_grp[b][s][j] = first;
            }
        }
        PBAR();

        // gather: 64 threads, 2 per row (half 0: cols 0..79's low 40; half 1: high 40)
        {
            int row = ptid >> 1;
            int half = ptid & 1;
            int idx = g_grp[b][s][row];
            const float4* fr = (const float4*)(fea + ((size_t)b * NPTS + idx) * FDIM);
            float f[40];
            if (half == 0) {
                float4 pc = __ldg(&g_p4[b][far]);
                float4 pi = __ldg(&g_p4[b][idx]);
                f[0] = pi.x - pc.x; f[1] = pi.y - pc.y; f[2] = pi.z - pc.z;
#pragma unroll
                for (int q = 0; q < 10; q++) {           // fea 0..39 -> f[3..42], use ..39
                    float4 vv = __ldg(fr + q);
                    if (3 + 4 * q     < 40) f[3 + 4 * q]     = vv.x;
                    if (3 + 4 * q + 1 < 40) f[3 + 4 * q + 1] = vv.y;
                    if (3 + 4 * q + 2 < 40) f[3 + 4 * q + 2] = vv.z;
                    if (3 + 4 * q + 3 < 40) f[3 + 4 * q + 3] = vv.w;
                }
#pragma unroll
                for (int q = 0; q < 20; q++)
                    storeA(aBase, row, 2 * q, f[2 * q], f[2 * q + 1]);
            } else {
                float4 v9 = __ldg(fr + 9);               // fea 36..39
                f[0] = v9.y; f[1] = v9.z; f[2] = v9.w;   // fea 37..39 -> cols 40..42
#pragma unroll
                for (int q = 0; q < 6; q++) {            // fea 40..63 -> cols 43..66
                    float4 vv = __ldg(fr + 10 + q);
                    f[3 + 4 * q]     = vv.x;
                    f[3 + 4 * q + 1] = vv.y;
                    f[3 + 4 * q + 2] = vv.z;
                    f[3 + 4 * q + 3] = vv.w;
                }
#pragma unroll
                for (int i = 27; i < 40; i++) f[i] = 0.f;
#pragma unroll
                for (int q = 0; q < 20; q++)
                    storeA(aBase, row, 40 + 2 * q, f[2 * q], f[2 * q + 1]);
            }
        }
        PBAR();

        // L1: [32x80] @ [80x64]
        {
            float acc[2][4][4];
            warp_gemm_ldg<4, 5>(aB, g_W1f, nhalf * 4, 5, acc);
            PBAR();
            epi_store<4>(aBase, nhalf * 32, B1, acc);
            PBAR();
        }
        // L2: [32x64] @ [64x128]
        {
            float acc[2][8][4];
            warp_gemm_ldg<8, 4>(aB, g_W2f, nhalf * 8, 4, acc);
            PBAR();
            epi_store<8>(aBase, nhalf * 64, B2, acc);
            PBAR();
        }
        // L3: [32x128] @ [128x256] as 4 barrier-free sub-GEMMs + maxpool
        size_t obase = (size_t)BATCH * NSAMP * 3 +
                       ((size_t)(b * NSAMP + s)) * 256;
        {
            float acc[2][4][4];
#pragma unroll
            for (int ci = 0; ci < 4; ci++) {
                warp_gemm_ldg<4, 8>(aB, g_W3f, ci * 8 + nhalf * 4, 8, acc);
                epi_max(ci * 64 + nhalf * 32, B3, out, obase, acc);
            }
        }
    }
#undef PBAR
}

// ---------------- launcher ----------------
extern "C" void kernel_launch(void* const* d_in, const int* in_sizes, int n_in,
                              void* d_out, int out_size) {
    (void)in_sizes; (void)n_in; (void)out_size;
    const float* xyz = (const float*)d_in[0];
    const float* fea = (const float*)d_in[1];
    const float* W1  = (const float*)d_in[2];
    const float* B1  = (const float*)d_in[3];
    const float* W2  = (const float*)d_in[4];
    const float* B2  = (const float*)d_in[5];
    const float* W3  = (const float*)d_in[6];
    const float* B3  = (const float*)d_in[7];
    float* out = (float*)d_out;

    cudaFuncSetAttribute(mega_kernel, cudaFuncAttributeMaxDynamicSharedMemorySize,
                         SMEM_TOT);

    init_kernel<<<200, 256>>>(W1, W2, W3);
    int grid = BATCH + 136;
    mega_kernel<<<grid, 512, SMEM_TOT>>>(xyz, fea, W1, B1, W2, B2, W3, B3, out);
}

// round 16
// speedup vs baseline: 3.3554x; 1.0620x over previous
#include <cuda_runtime.h>
#include <cuda_bf16.h>
#include <cstdint>
#include <cstddef>

#define BATCH 16
#define NPTS  8192
#define NSAMP 1024
#define NGRP  32
#define FDIM  64
#define NITEM (BATCH * NSAMP)            // 16384 single-centroid work items

// ---------------- device scratch ----------------
__device__ float4 g_p4[BATCH][NPTS];     // x,y,z,sumsq
__device__ int    g_fps[BATCH][NSAMP];
__device__ int    g_grp[BATCH][NSAMP][NGRP];
__device__ int    g_prog[BATCH];
__device__ int    g_qhead;

// B fragments pre-packed per mma lane: uint4 = {b0_hi, b1_hi, b0_lo, b1_lo}
__device__ uint4 g_W1f[8 * 5 * 32];
__device__ uint4 g_W2f[16 * 4 * 32];
__device__ uint4 g_W3f[32 * 8 * 32];

static __device__ __forceinline__ unsigned pkbf(float a, float b) {
    __nv_bfloat16 ha = __float2bfloat16(a), hb = __float2bfloat16(b);
    return (unsigned)__bfloat16_as_ushort(ha) |
           ((unsigned)__bfloat16_as_ushort(hb) << 16);
}
static __device__ __forceinline__ uint4 packfrag(const float* W, int K, int ldw,
                                                 int nbg, int kb, int l) {
    int n = nbg * 8 + (l >> 2);
    int k = kb * 16 + 2 * (l & 3);
    float w0 = (k     < K) ? __ldg(W + k * ldw + n)       : 0.f;
    float w1 = (k + 1 < K) ? __ldg(W + (k + 1) * ldw + n) : 0.f;
    float w8 = (k + 8 < K) ? __ldg(W + (k + 8) * ldw + n) : 0.f;
    float w9 = (k + 9 < K) ? __ldg(W + (k + 9) * ldw + n) : 0.f;
    float r0 = w0 - __bfloat162float(__float2bfloat16(w0));
    float r1 = w1 - __bfloat162float(__float2bfloat16(w1));
    float r8 = w8 - __bfloat162float(__float2bfloat16(w8));
    float r9 = w9 - __bfloat162float(__float2bfloat16(w9));
    uint4 o;
    o.x = pkbf(w0, w1); o.y = pkbf(w8, w9);
    o.z = pkbf(r0, r1); o.w = pkbf(r8, r9);
    return o;
}

__global__ void init_kernel(const float* __restrict__ W1,
                            const float* __restrict__ W2,
                            const float* __restrict__ W3) {
    int nth = gridDim.x * blockDim.x;
    int i = blockIdx.x * blockDim.x + threadIdx.x;
    if (i < BATCH) g_prog[i] = 0;
    if (i == BATCH) g_qhead = 0;
    for (int idx = i; idx < 8 * 5 * 32; idx += nth) {
        int l = idx & 31, kb = (idx >> 5) % 5, nbg = idx / 160;
        g_W1f[idx] = packfrag(W1, 67, 64, nbg, kb, l);
    }
    for (int idx = i; idx < 16 * 4 * 32; idx += nth) {
        int l = idx & 31, kb = (idx >> 5) & 3, nbg = idx >> 7;
        g_W2f[idx] = packfrag(W2, 64, 128, nbg, kb, l);
    }
    for (int idx = i; idx < 32 * 8 * 32; idx += nth) {
        int l = idx & 31, kb = (idx >> 5) & 7, nbg = idx >> 8;
        g_W3f[idx] = packfrag(W3, 128, 256, nbg, kb, l);
    }
}

// =====================================================================
// SMEM (dynamic, 139264 B):
//  consumer: pair p (0..7): A hi @ p*8704 ([32][136] bf16), A lo @ +69632
//  fps: sx/sy/sz[8192] f32, sidx[8192] i32, sspos[1024], cnt[512], base[512]
// =====================================================================
#define LDA       136
#define ALO_GAP   69632
#define PAIR_A    8704
#define SMEM_TOT  139264

static __device__ __forceinline__ uint32_t smem_u32(const void* p) {
    uint32_t a;
    asm("{ .reg .u64 t; cvta.to.shared.u64 t, %1; cvt.u32.u64 %0, t; }"
        : "=r"(a) : "l"(p));
    return a;
}
static __device__ __forceinline__ void ldm_x4(uint32_t* r, uint32_t addr) {
    asm volatile("ldmatrix.sync.aligned.m8n8.x4.shared.b16 {%0,%1,%2,%3}, [%4];"
                 : "=r"(r[0]), "=r"(r[1]), "=r"(r[2]), "=r"(r[3]) : "r"(addr));
}
static __device__ __forceinline__ void mma_bf16(float* c, const uint32_t* a,
                                                uint32_t b0, uint32_t b1) {
    asm volatile(
        "mma.sync.aligned.m16n8k16.row.col.f32.bf16.bf16.f32 "
        "{%0,%1,%2,%3}, {%4,%5,%6,%7}, {%8,%9}, {%0,%1,%2,%3};"
        : "+f"(c[0]), "+f"(c[1]), "+f"(c[2]), "+f"(c[3])
        : "r"(a[0]), "r"(a[1]), "r"(a[2]), "r"(a[3]), "r"(b0), "r"(b1));
}

// fast bf16x2 pack: lo-half = a, hi-half = b (cvt.rn == scalar __float2bfloat16)
static __device__ __forceinline__ unsigned pack2(float a, float b) {
    unsigned r;
    asm("cvt.rn.bf16x2.f32 %0, %1, %2;" : "=r"(r) : "f"(b), "f"(a));
    return r;
}
// bit-exact fast split (6 instr): hi = pack(a,b); lo = pack(a-hi.a, b-hi.b)
static __device__ __forceinline__ void split2(float a, float b,
                                              unsigned& hi, unsigned& lo) {
    hi = pack2(a, b);
    float ah = __uint_as_float(hi << 16);          // bf16->f32 == shift left 16
    float bh = __uint_as_float(hi & 0xffff0000u);
    lo = pack2(a - ah, b - bh);
}
static __device__ __forceinline__ void storeA(char* aBase, int row, int col,
                                              float a, float b) {
    unsigned h, l;
    split2(a, b, h, l);
    int off = (row * LDA + col) * 2;
    *(unsigned*)(aBase + off) = h;
    *(unsigned*)(aBase + ALO_GAP + off) = l;
}

// warp GEMM over the pair's 32 rows; B fragments from packed global arrays.
// NBLK==4: next-k software prefetch of B; NBLK==8: LDG-first per k-step.
template <int NBLK, int KSTEPS>
static __device__ __forceinline__ void warp_gemm_ldg(
    uint32_t aB, const uint4* __restrict__ Wf, int nbgBase, int KB,
    float (&acc)[2][NBLK][4])
{
    int lane = threadIdx.x & 31;
#pragma unroll
    for (int m = 0; m < 2; m++)
#pragma unroll
        for (int nb = 0; nb < NBLK; nb++)
#pragma unroll
            for (int i = 0; i < 4; i++) acc[m][nb][i] = 0.f;

    int arow = lane & 15;
    int acolo = (lane >> 4) << 3;
    const uint4* base = Wf + (size_t)nbgBase * KB * 32 + lane;

    if constexpr (NBLK == 4) {
        uint4 f[4], fn[4];
#pragma unroll
        for (int q = 0; q < 4; q++) f[q] = __ldg(base + (size_t)q * KB * 32);
#pragma unroll
        for (int k = 0; k < KSTEPS; k++) {
            int k0 = k << 4;
            uint32_t ah[2][4], al[2][4];
#pragma unroll
            for (int m = 0; m < 2; m++) {
                uint32_t ao = (uint32_t)(((m * 16 + arow) * LDA + k0 + acolo) * 2);
                ldm_x4(ah[m], aB + ao);
                ldm_x4(al[m], aB + ALO_GAP + ao);
            }
            if (k + 1 < KSTEPS) {
#pragma unroll
                for (int q = 0; q < 4; q++)
                    fn[q] = __ldg(base + ((size_t)q * KB + k + 1) * 32);
            }
#pragma unroll
            for (int q = 0; q < 4; q++) {
#pragma unroll
                for (int m = 0; m < 2; m++) {
                    mma_bf16(acc[m][q], ah[m], f[q].x, f[q].y);
                    mma_bf16(acc[m][q], ah[m], f[q].z, f[q].w);
                    mma_bf16(acc[m][q], al[m], f[q].x, f[q].y);
                }
            }
            if (k + 1 < KSTEPS) {
#pragma unroll
                for (int q = 0; q < 4; q++) f[q] = fn[q];
            }
        }
    } else {
#pragma unroll
        for (int k = 0; k < KSTEPS; k++) {
            int k0 = k << 4;
            uint4 f[NBLK];
#pragma unroll
            for (int q = 0; q < NBLK; q++)
                f[q] = __ldg(base + ((size_t)q * KB + k) * 32);
            uint32_t ah[2][4], al[2][4];
#pragma unroll
            for (int m = 0; m < 2; m++) {
                uint32_t ao = (uint32_t)(((m * 16 + arow) * LDA + k0 + acolo) * 2);
                ldm_x4(ah[m], aB + ao);
                ldm_x4(al[m], aB + ALO_GAP + ao);
            }
#pragma unroll
            for (int q = 0; q < NBLK; q++) {
#pragma unroll
                for (int m = 0; m < 2; m++) {
                    mma_bf16(acc[m][q], ah[m], f[q].x, f[q].y);
                    mma_bf16(acc[m][q], ah[m], f[q].z, f[q].w);
                    mma_bf16(acc[m][q], al[m], f[q].x, f[q].y);
                }
            }
        }
    }
}

template <int NBLK>
static __device__ __forceinline__ void epi_store(char* aBase, int colBase,
                                                 const float* __restrict__ bias,
                                                 float (&acc)[2][NBLK][4]) {
    int lane = threadIdx.x & 31;
    int cq = (lane & 3) * 2;
    int rq = lane >> 2;
#pragma unroll
    for (int nb = 0; nb < NBLK; nb++) {
        int col = colBase + nb * 8 + cq;
        float b0 = __ldg(bias + col), b1 = __ldg(bias + col + 1);
#pragma unroll
        for (int m = 0; m < 2; m++) {
            int row = m * 16 + rq;
            float v0 = fmaxf(acc[m][nb][0] + b0, 0.f);
            float v1 = fmaxf(acc[m][nb][1] + b1, 0.f);
            float v2 = fmaxf(acc[m][nb][2] + b0, 0.f);
            float v3 = fmaxf(acc[m][nb][3] + b1, 0.f);
            storeA(aBase, row, col, v0, v1);
            storeA(aBase, row + 8, col, v2, v3);
        }
    }
}

static __device__ __forceinline__ void epi_max(int gColBase, const float* __restrict__ B3,
                                               float* __restrict__ out, size_t obase,
                                               float (&acc)[2][4][4]) {
    int lane = threadIdx.x & 31;
    int cq = (lane & 3) * 2;
#pragma unroll
    for (int nb = 0; nb < 4; nb++) {
        int col = gColBase + nb * 8 + cq;
        float b0 = __ldg(B3 + col), b1 = __ldg(B3 + col + 1);
        float v0 = fmaxf(fmaxf(acc[0][nb][0], acc[0][nb][2]),
                         fmaxf(acc[1][nb][0], acc[1][nb][2])) + b0;
        float v1 = fmaxf(fmaxf(acc[0][nb][1], acc[0][nb][3]),
                         fmaxf(acc[1][nb][1], acc[1][nb][3])) + b1;
        v0 = fmaxf(v0, 0.f); v1 = fmaxf(v1, 0.f);
#pragma unroll
        for (int off = 4; off <= 16; off <<= 1) {
            v0 = fmaxf(v0, __shfl_xor_sync(0xffffffffu, v0, off));
            v1 = fmaxf(v1, __shfl_xor_sync(0xffffffffu, v1, off));
        }
        if (lane < 4) {
            out[obase + col] = v0;
            out[obase + col + 1] = v1;
        }
    }
}

static __device__ __forceinline__ unsigned spread3(unsigned v) {
    return (v & 1u) | ((v & 2u) << 2) | ((v & 4u) << 4);
}

// =====================================================================
// mega kernel: blocks 0..15 run Morton-pruned FPS then convert; all
// consumer blocks = 8 independent warp-PAIR pipelines, 1 centroid/item.
// =====================================================================
__global__ void __launch_bounds__(512, 1) mega_kernel(
    const float* __restrict__ xyz, const float* __restrict__ fea,
    const float* __restrict__ W1, const float* __restrict__ B1,
    const float* __restrict__ W2, const float* __restrict__ B2,
    const float* __restrict__ W3, const float* __restrict__ B3,
    float* __restrict__ out)
{
    extern __shared__ char smp[];
    __shared__ uint2 s_wk[2][16];
    __shared__ int s_item[8];
    __shared__ int s_far0;

    if (blockIdx.x < BATCH) {
        // ================= FPS role (Morton-sorted, box-pruned) =========
        float* sx = (float*)smp;
        float* sy = sx + NPTS;
        float* sz = sy + NPTS;
        int* sidx = (int*)(sz + NPTS);
        int* sspos = sidx + NPTS;
        int* scnt = sspos + NSAMP;
        int* sbase = scnt + 512;

        int b = blockIdx.x, t = threadIdx.x;
        int lane = t & 31, warp = t >> 5;

        float px[16], py[16], pz[16], dist[16];
        int cid[16];
        if (t < 512) scnt[t] = 0;
        __syncthreads();
#pragma unroll
        for (int j = 0; j < 16; j++) {
            int p = t + 512 * j;
            const float* src = xyz + ((size_t)b * NPTS + p) * 3;
            float x = src[0], y = src[1], z = src[2];
            px[j] = x; py[j] = y; pz[j] = z;
            g_p4[b][p] = make_float4(x, y, z,
                __fmaf_rn(z, z, __fmaf_rn(y, y, __fmul_rn(x, x))));
            unsigned ix = min(7, (int)(x * 8.f));
            unsigned iy = min(7, (int)(y * 8.f));
            unsigned iz = min(7, (int)(z * 8.f));
            cid[j] = (int)(spread3(ix) | (spread3(iy) << 1) | (spread3(iz) << 2));
            atomicAdd(&scnt[cid[j]], 1);
        }
        __threadfence();
        __syncthreads();
        if (warp == 0) {
            int c0 = lane * 16, s = 0;
#pragma unroll
            for (int i = 0; i < 16; i++) s += scnt[c0 + i];
            int off = s;
#pragma unroll
            for (int d = 1; d < 32; d <<= 1) {
                int n = __shfl_up_sync(0xffffffffu, off, d);
                if (lane >= d) off += n;
            }
            off -= s;
            int run = off;
#pragma unroll
            for (int i = 0; i < 16; i++) {
                int c = scnt[c0 + i];
                sbase[c0 + i] = run;
                run += c;
            }
        }
        __syncthreads();
#pragma unroll
        for (int j = 0; j < 16; j++) {
            int pos = atomicAdd(&sbase[cid[j]], 1);
            sx[pos] = px[j]; sy[pos] = py[j]; sz[pos] = pz[j];
            sidx[pos] = t + 512 * j;
            if (t == 0 && j == 0) s_far0 = pos;
        }
        __syncthreads();
        float lox = 1e9f, hix = -1e9f, loy = 1e9f, hiy = -1e9f,
              loz = 1e9f, hiz = -1e9f;
#pragma unroll
        for (int j = 0; j < 16; j++) {
            int p = 16 * t + j;
            float x = sx[p], y = sy[p], z = sz[p];
            px[j] = x; py[j] = y; pz[j] = z; dist[j] = 1e10f;
            lox = fminf(lox, x); hix = fmaxf(hix, x);
            loy = fminf(loy, y); hiy = fmaxf(hiy, y);
            loz = fminf(loz, z); hiz = fmaxf(hiz, z);
        }
        float tmax = 1e10f;
        int far_orig = 0, far_spos = s_far0;

        for (int k = 0; k < NSAMP; k++) {
            if (t == 0) { g_fps[b][k] = far_orig; sspos[k] = far_spos; }
            float cx = sx[far_spos], cy = sy[far_spos], cz = sz[far_spos];

            float dxl = fmaxf(fmaxf(__fsub_rn(lox, cx), __fsub_rn(cx, hix)), 0.f);
            float dyl = fmaxf(fmaxf(__fsub_rn(loy, cy), __fsub_rn(cy, hiy)), 0.f);
            float dzl = fmaxf(fmaxf(__fsub_rn(loz, cz), __fsub_rn(cz, hiz)), 0.f);
            float bound = dxl * dxl + dyl * dyl + dzl * dzl;

            if (!(bound * 0.999f > tmax)) {
                float nm = 0.f;
#pragma unroll
                for (int j = 0; j < 16; j++) {
                    float dx = __fsub_rn(px[j], cx);
                    float dy = __fsub_rn(py[j], cy);
                    float dz = __fsub_rn(pz[j], cz);
                    float d = __fmaf_rn(dz, dz, __fmaf_rn(dy, dy, __fmul_rn(dx, dx)));
                    float dm = fminf(dist[j], d);
                    dist[j] = dm;
                    nm = fmaxf(nm, dm);
                }
                tmax = nm;
            }
            unsigned tb = __float_as_uint(tmax);
            unsigned wmax = __reduce_max_sync(0xffffffffu, tb);
            unsigned cand = 0xffffffffu;
            if (tb == wmax) {
#pragma unroll
                for (int j = 0; j < 16; j++)
                    if (__float_as_uint(dist[j]) == wmax) {
                        int sp = 16 * t + j;
                        unsigned key = ((unsigned)sidx[sp] << 13) | (unsigned)sp;
                        cand = min(cand, key);
                    }
            }
            unsigned widx = __reduce_min_sync(0xffffffffu, cand);
            if (lane == 0) s_wk[k & 1][warp] = make_uint2(wmax, widx);
            __syncthreads();
            uint2 v = (lane < 16) ? s_wk[k & 1][lane] : make_uint2(0u, 0xffffffffu);
            unsigned m2 = __reduce_max_sync(0xffffffffu, v.x);
            unsigned c2 = (v.x == m2) ? v.y : 0xffffffffu;
            c2 = __reduce_min_sync(0xffffffffu, c2);
            far_orig = (int)(c2 >> 13);
            far_spos = (int)(c2 & 8191u);

            if (t == 0 && ((k + 1) & 7) == 0) {
                __threadfence();
                *(volatile int*)&g_prog[b] = k + 1;
            }
        }
        __syncthreads();
        for (int k = t; k < NSAMP; k += 512) {
            int sp = sspos[k];
            size_t o = ((size_t)b * NSAMP + k) * 3;
            out[o + 0] = sx[sp];
            out[o + 1] = sy[sp];
            out[o + 2] = sz[sp];
        }
        __syncthreads();
        // fall through: convert to consumer
    }

    // ========== persistent consumers: 8 independent warp-pair pipelines ====
    uint32_t sb = smem_u32(smp);
    int tid = threadIdx.x, lane = tid & 31;
    int wid = tid >> 5;
    int pair = wid >> 1;
    int nhalf = wid & 1;
    int ptid = tid & 63;                 // id within pair

    char* aBase = smp + pair * PAIR_A;
    uint32_t aB = sb + pair * PAIR_A;
    int barid = 1 + pair;
#define PBAR() asm volatile("bar.sync %0, 64;" :: "r"(barid) : "memory")

    for (;;) {
        if (ptid == 0) {
            int v = atomicAdd(&g_qhead, 1);
            if (v < NITEM) {
                int bb = v & 15, need = (v >> 4) + 1;
                while (*(volatile int*)&g_prog[bb] < need) __nanosleep(128);
                __threadfence();
            }
            s_item[pair] = v;
        }
        PBAR();
        int v = s_item[pair];
        if (v >= NITEM) break;
        int b = v & 15;
        int s = v >> 4;
        int far = __ldcg(&g_fps[b][s]);

        // ballq by even warp of the pair
        if (nhalf == 0) {
            float4 c4 = __ldg(&g_p4[b][far]);
            float ax = c4.x, ay = c4.y, az = c4.z, sa = c4.w;
            const float RR = 0.04f;
            int filled = 0;
            for (int base = 0; base < NPTS; base += 32) {
                int n = base + lane;
                float4 p = __ldg(&g_p4[b][n]);
                float dot = __fmaf_rn(az, p.z, __fmaf_rn(ay, p.y, __fmul_rn(ax, p.x)));
                float sq = __fsub_rn(__fadd_rn(sa, p.w), __fmul_rn(2.0f, dot));
                bool inr = !(sq > RR);
                unsigned m = __ballot_sync(0xffffffffu, inr);
                int pos = filled + __popc(m & ((1u << lane) - 1u));
                if (inr && pos < NGRP) g_grp[b][s][pos] = n;
                filled += __popc(m);
                if (filled >= NGRP) break;
            }
            if (filled < NGRP) {
                __syncwarp();
                int first = g_grp[b][s][0];
                int j = filled + lane;
                if (j < NGRP) g_grp[b][s][j] = first;
            }
        }
        PBAR();

        // gather: 64 threads, 2 per row (half 0: cols 0..39; half 1: cols 40..79)
        {
            int row = ptid >> 1;
            int half = ptid & 1;
            int idx = g_grp[b][s][row];
            const float4* fr = (const float4*)(fea + ((size_t)b * NPTS + idx) * FDIM);
            float f[40];
            if (half == 0) {
                float4 pc = __ldg(&g_p4[b][far]);
                float4 pi = __ldg(&g_p4[b][idx]);
                f[0] = pi.x - pc.x; f[1] = pi.y - pc.y; f[2] = pi.z - pc.z;
#pragma unroll
                for (int q = 0; q < 10; q++) {
                    float4 vv = __ldg(fr + q);
                    if (3 + 4 * q     < 40) f[3 + 4 * q]     = vv.x;
                    if (3 + 4 * q + 1 < 40) f[3 + 4 * q + 1] = vv.y;
                    if (3 + 4 * q + 2 < 40) f[3 + 4 * q + 2] = vv.z;
                    if (3 + 4 * q + 3 < 40) f[3 + 4 * q + 3] = vv.w;
                }
#pragma unroll
                for (int q = 0; q < 20; q++)
                    storeA(aBase, row, 2 * q, f[2 * q], f[2 * q + 1]);
            } else {
                float4 v9 = __ldg(fr + 9);
                f[0] = v9.y; f[1] = v9.z; f[2] = v9.w;
#pragma unroll
                for (int q = 0; q < 6; q++) {
                    float4 vv = __ldg(fr + 10 + q);
                    f[3 + 4 * q]     = vv.x;
                    f[3 + 4 * q + 1] = vv.y;
                    f[3 + 4 * q + 2] = vv.z;
                    f[3 + 4 * q + 3] = vv.w;
                }
#pragma unroll
                for (int i = 27; i < 40; i++) f[i] = 0.f;
#pragma unroll
                for (int q = 0; q < 20; q++)
                    storeA(aBase, row, 40 + 2 * q, f[2 * q], f[2 * q + 1]);
            }
        }
        PBAR();

        // L1: [32x80] @ [80x64]
        {
            float acc[2][4][4];
            warp_gemm_ldg<4, 5>(aB, g_W1f, nhalf * 4, 5, acc);
            PBAR();
            epi_store<4>(aBase, nhalf * 32, B1, acc);
            PBAR();
        }
        // L2: [32x64] @ [64x128]
        {
            float acc[2][8][4];
            warp_gemm_ldg<8, 4>(aB, g_W2f, nhalf * 8, 4, acc);
            PBAR();
            epi_store<8>(aBase, nhalf * 64, B2, acc);
            PBAR();
        }
        // L3: [32x128] @ [128x256] as 4 barrier-free sub-GEMMs + maxpool
        size_t obase = (size_t)BATCH * NSAMP * 3 +
                       ((size_t)(b * NSAMP + s)) * 256;
        {
            float acc[2][4][4];
#pragma unroll
            for (int ci = 0; ci < 4; ci++) {
                warp_gemm_ldg<4, 8>(aB, g_W3f, ci * 8 + nhalf * 4, 8, acc);
                epi_max(ci * 64 + nhalf * 32, B3, out, obase, acc);
            }
        }
    }
#undef PBAR
}

// ---------------- launcher ----------------
extern "C" void kernel_launch(void* const* d_in, const int* in_sizes, int n_in,
                              void* d_out, int out_size) {
    (void)in_sizes; (void)n_in; (void)out_size;
    const float* xyz = (const float*)d_in[0];
    const float* fea = (const float*)d_in[1];
    const float* W1  = (const float*)d_in[2];
    const float* B1  = (const float*)d_in[3];
    const float* W2  = (const float*)d_in[4];
    const float* B2  = (const float*)d_in[5];
    const float* W3  = (const float*)d_in[6];
    const float* B3  = (const float*)d_in[7];
    float* out = (float*)d_out;

    cudaFuncSetAttribute(mega_kernel, cudaFuncAttributeMaxDynamicSharedMemorySize,
                         SMEM_TOT);

    init_kernel<<<200, 256>>>(W1, W2, W3);
    int grid = BATCH + 136;
    mega_kernel<<<grid, 512, SMEM_TOT>>>(xyz, fea, W1, B1, W2, B2, W3, B3, out);
}